// round 1
// baseline (speedup 1.0000x reference)
#include <cuda_runtime.h>
#include <cstdint>

#define BB 16
#define HH 128
#define WW 128
#define CC 256
#define KK 32
#define NPIX (HH*WW)
#define NCLS 21
#define BN_EPS 1e-3f

#define TPB 256
#define TILE_P 64
#define BLOCKS_PER_BATCH 32
#define TILES_PER_BLOCK ((NPIX/TILE_P)/BLOCKS_PER_BATCH)  // 8

// Scratch (no allocations allowed)
__device__ float g_agg[BB*KK*CC];   // sum_n w[n,k] * x[n,c]
__device__ float g_wsum[BB*KK];     // sum_n w[n,k]
__device__ float g_attn[BB*CC];
__device__ float g_c2[KK];

// ---- packed f32x2 helpers (FFMA2 path) ----
__device__ __forceinline__ void fma2(unsigned long long &d, unsigned long long a, unsigned long long b){
    asm("fma.rn.f32x2 %0, %1, %2, %0;" : "+l"(d) : "l"(a), "l"(b));
}
__device__ __forceinline__ unsigned long long pack2(float a, float b){
    unsigned long long r;
    asm("mov.b64 %0, {%1, %2};" : "=l"(r) : "r"(__float_as_uint(a)), "r"(__float_as_uint(b)));
    return r;
}
__device__ __forceinline__ float2 unpack2(unsigned long long v){
    unsigned int lo, hi;
    asm("mov.b64 {%0, %1}, %2;" : "=r"(lo), "=r"(hi) : "l"(v));
    return make_float2(__uint_as_float(lo), __uint_as_float(hi));
}

// ---------------- init: zero scratch, codeword squared norms ----------------
__global__ void k_init(const float* __restrict__ cw){
    int t = blockIdx.x*blockDim.x + threadIdx.x;
    if (t < BB*KK*CC) g_agg[t] = 0.f;
    int t2 = t - BB*KK*CC;
    if (t2 >= 0 && t2 < BB*KK) g_wsum[t2] = 0.f;
    if (t < KK){
        float s = 0.f;
        #pragma unroll 8
        for (int c = 0; c < CC; c++){ float v = cw[t*CC + c]; s += v*v; }
        g_c2[t] = s;
    }
}

// ---------------- fused: distances -> softmax -> aggregation ----------------
// smem layout (floats):
//   [0,16384)      x tile      [64][256]
//   [16384,24576)  cw4         [c4=64][k=32] as float4 groups: cw[k][4c4..4c4+3]
//   [24576,26624)  w tile      [64][32]
//   [26624,26688)  x2          [64]
//   [26688,26944)  x2 partials [256]
//   [26944,26976)  c2          [32]
//   [26976,27008)  smoothing   [32]
#define SMEM_FLOATS 27008
#define SMEM_BYTES  (SMEM_FLOATS*4)

__global__ __launch_bounds__(TPB, 2) void k_encode(
    const float* __restrict__ x,
    const float* __restrict__ cw,
    const float* __restrict__ smo)
{
    extern __shared__ float smem[];
    float* sm_x   = smem;
    float* sm_cw  = smem + 16384;
    float* sm_w   = smem + 24576;
    float* sm_x2  = smem + 26624;
    float* sm_x2p = smem + 26688;
    float* sm_c2  = smem + 26944;
    float* sm_s   = smem + 26976;

    const int t = threadIdx.x;
    const int b = blockIdx.y;
    const int lane = t & 31;
    const int warp = t >> 5;

    // codewords -> smem, layout cw4[c4][k] (conflict-free k-strided reads)
    #pragma unroll
    for (int i = 0; i < 8; i++){
        int idx = t + i*TPB;               // 0..2047
        int k  = idx >> 6;
        int c4 = idx & 63;
        float4 v = ((const float4*)cw)[k*64 + c4];
        ((float4*)sm_cw)[c4*32 + k] = v;
    }
    if (t < KK){ sm_c2[t] = g_c2[t]; sm_s[t] = smo[t]; }

    // persistent aggregation accumulators: thread owns 4 k x 8 c (as 16 f32x2)
    unsigned long long accC[4][4];
    #pragma unroll
    for (int i = 0; i < 4; i++)
        #pragma unroll
        for (int j = 0; j < 4; j++) accC[i][j] = 0ULL;
    float wsum_loc = 0.f;

    const int p0  = warp * 8;          // phase B: 8 pixels per warp
    const int k0  = (t & 7) * 4;       // phase C k group
    const int cg2 = (t >> 3) * 2;      // phase C c group (ulonglong2 units)

    for (int tile = 0; tile < TILES_PER_BLOCK; tile++){
        __syncthreads();  // previous phase C done with sm_x / sm_w (and cw load on tile 0)

        // ---- Phase A: load 64x256 x tile ----
        const int pbase = blockIdx.x * (TILE_P*TILES_PER_BLOCK) + tile*TILE_P;
        const float4* xg = (const float4*)(x + (size_t)(b*NPIX + pbase)*CC);
        #pragma unroll
        for (int i = 0; i < 16; i++){
            int idx = t + i*TPB;
            ((float4*)sm_x)[idx] = xg[idx];
        }
        __syncthreads();

        // ---- x^2 per pixel ----
        {
            int p = t >> 2, q = t & 3;
            const float4* xr = ((const float4*)(sm_x + p*CC)) + q*16;
            float s = 0.f;
            #pragma unroll
            for (int i = 0; i < 16; i++){
                float4 v = xr[i];
                s += v.x*v.x + v.y*v.y + v.z*v.z + v.w*v.w;
            }
            sm_x2p[t] = s;
        }
        __syncthreads();
        if (t < TILE_P)
            sm_x2[t] = sm_x2p[t*4] + sm_x2p[t*4+1] + sm_x2p[t*4+2] + sm_x2p[t*4+3];
        __syncthreads();

        // ---- Phase B: dots (lane = k), softmax across warp ----
        {
            unsigned long long acc[8];
            #pragma unroll
            for (int i = 0; i < 8; i++) acc[i] = 0ULL;
            const ulonglong2* xu = (const ulonglong2*)sm_x;   // [p][64]
            const ulonglong2* cu = (const ulonglong2*)sm_cw;  // [c4][32]
            #pragma unroll 4
            for (int c4 = 0; c4 < 64; c4++){
                ulonglong2 cv = cu[c4*32 + lane];
                #pragma unroll
                for (int pp = 0; pp < 8; pp++){
                    ulonglong2 xv = xu[(p0+pp)*64 + c4];
                    fma2(acc[pp], cv.x, xv.x);
                    fma2(acc[pp], cv.y, xv.y);
                }
            }
            float c2k = sm_c2[lane];
            float sk  = sm_s[lane];
            #pragma unroll
            for (int pp = 0; pp < 8; pp++){
                float2 f = unpack2(acc[pp]);
                float dot = f.x + f.y;
                float lg = (sm_x2[p0+pp] - 2.f*dot + c2k) * sk;
                float m = lg;
                #pragma unroll
                for (int o = 16; o > 0; o >>= 1)
                    m = fmaxf(m, __shfl_xor_sync(0xffffffffu, m, o));
                float e = __expf(lg - m);
                float s = e;
                #pragma unroll
                for (int o = 16; o > 0; o >>= 1)
                    s += __shfl_xor_sync(0xffffffffu, s, o);
                float wv = e / s;
                sm_w[(p0+pp)*32 + lane] = wv;
                wsum_loc += wv;
            }
        }
        __syncthreads();

        // ---- Phase C: agg[k][c] += w[p][k] * x[p][c] ----
        {
            const ulonglong2* xu = (const ulonglong2*)sm_x;
            #pragma unroll 4
            for (int p = 0; p < TILE_P; p++){
                float4 w4 = *(const float4*)(sm_w + p*32 + k0);
                unsigned long long wp[4];
                wp[0] = pack2(w4.x, w4.x);
                wp[1] = pack2(w4.y, w4.y);
                wp[2] = pack2(w4.z, w4.z);
                wp[3] = pack2(w4.w, w4.w);
                ulonglong2 xa = xu[p*64 + cg2];
                ulonglong2 xb = xu[p*64 + cg2 + 1];
                #pragma unroll
                for (int i = 0; i < 4; i++){
                    fma2(accC[i][0], wp[i], xa.x);
                    fma2(accC[i][1], wp[i], xa.y);
                    fma2(accC[i][2], wp[i], xb.x);
                    fma2(accC[i][3], wp[i], xb.y);
                }
            }
        }
    }

    // ---- flush ----
    const int c0 = (t >> 3) * 8;
    #pragma unroll
    for (int i = 0; i < 4; i++)
        #pragma unroll
        for (int j = 0; j < 4; j++){
            float2 f = unpack2(accC[i][j]);
            float* dst = &g_agg[(b*KK + k0 + i)*CC + c0 + j*2];
            atomicAdd(dst,     f.x);
            atomicAdd(dst + 1, f.y);
        }
    atomicAdd(&g_wsum[b*KK + lane], wsum_loc);
}

// ---------------- BN + ReLU + enc, attention + SE heads ----------------
__global__ void k_heads(
    const float* __restrict__ cw,
    const float* __restrict__ gamma, const float* __restrict__ beta,
    const float* __restrict__ mean,  const float* __restrict__ var,
    const float* __restrict__ Wenc,  const float* __restrict__ benc,
    const float* __restrict__ Wse,   const float* __restrict__ bse,
    float* __restrict__ out)
{
    const int b = blockIdx.x;
    const int c = threadIdx.x;
    __shared__ float enc[CC];

    float acc = 0.f;
    #pragma unroll
    for (int k = 0; k < KK; k++){
        float a  = g_agg[(b*KK + k)*CC + c] - g_wsum[b*KK + k] * cw[k*CC + c];
        float bn = (a - mean[k]) * rsqrtf(var[k] + BN_EPS) * gamma[k] + beta[k];
        acc += fmaxf(bn, 0.f);
    }
    enc[c] = acc;
    __syncthreads();

    float s = benc[c];
    #pragma unroll 8
    for (int i = 0; i < CC; i++) s += enc[i] * Wenc[i*CC + c];
    g_attn[b*CC + c] = 1.f / (1.f + __expf(-s));

    if (c < NCLS){
        float s2 = bse[c];
        #pragma unroll 8
        for (int i = 0; i < CC; i++) s2 += enc[i] * Wse[i*NCLS + c];
        out[(size_t)BB*NPIX*CC + b*NCLS + c] = 1.f / (1.f + __expf(-s2));
    }
}

// ---------------- rescale featuremaps ----------------
__global__ void k_scale(const float* __restrict__ x, float* __restrict__ out){
    const int F4 = NPIX*CC/4;   // float4 per batch = 1048576
    int idx = blockIdx.x*blockDim.x + threadIdx.x;   // 0..16777215
    int b  = idx / F4;
    int r  = idx - b*F4;
    int c4 = r & 63;
    float4 a = ((const float4*)g_attn)[b*64 + c4];
    float4 v = ((const float4*)x)[idx];
    v.x *= a.x; v.y *= a.y; v.z *= a.z; v.w *= a.w;
    ((float4*)out)[idx] = v;
}

extern "C" void kernel_launch(void* const* d_in, const int* in_sizes, int n_in,
                              void* d_out, int out_size)
{
    const float* x     = (const float*)d_in[0];
    const float* cw    = (const float*)d_in[1];
    const float* smo   = (const float*)d_in[2];
    const float* gamma = (const float*)d_in[3];
    const float* beta  = (const float*)d_in[4];
    const float* mean  = (const float*)d_in[5];
    const float* var   = (const float*)d_in[6];
    const float* Wenc  = (const float*)d_in[7];
    const float* benc  = (const float*)d_in[8];
    const float* Wse   = (const float*)d_in[9];
    const float* bse   = (const float*)d_in[10];
    float* out = (float*)d_out;

    cudaFuncSetAttribute(k_encode, cudaFuncAttributeMaxDynamicSharedMemorySize, SMEM_BYTES);

    int init_total = BB*KK*CC + BB*KK;
    k_init<<<(init_total + TPB - 1)/TPB, TPB>>>(cw);
    k_encode<<<dim3(BLOCKS_PER_BATCH, BB), TPB, SMEM_BYTES>>>(x, cw, smo);
    k_heads<<<BB, CC>>>(cw, gamma, beta, mean, var, Wenc, benc, Wse, bse, out);
    k_scale<<<(BB*NPIX*CC/4)/TPB, TPB>>>(x, out);
}

// round 2
// speedup vs baseline: 1.1196x; 1.1196x over previous
#include <cuda_runtime.h>
#include <cstdint>

#define BB 16
#define HH 128
#define WW 128
#define CC 256
#define KK 32
#define NPIX (HH*WW)
#define NCLS 21
#define BN_EPS 1e-3f

#define TPB 512
#define TILE_P 64
#define TILES_TOTAL (BB*(NPIX/TILE_P))   // 4096
#define GRID_ENC 592                      // 148 SMs * 2 blocks * 2 waves
#define TILES_PER_BLOCK 7                 // ceil(4096/592)

// Scratch (no allocations allowed)
__device__ float g_agg[BB*KK*CC];
__device__ float g_wsum[BB*KK];
__device__ float g_attn[BB*CC];
__device__ float g_c2[KK];

// ---- packed f32x2 helpers ----
__device__ __forceinline__ void fma2(unsigned long long &d, unsigned long long a, unsigned long long b){
    asm("fma.rn.f32x2 %0, %1, %2, %0;" : "+l"(d) : "l"(a), "l"(b));
}
__device__ __forceinline__ unsigned long long pack2(float a, float b){
    unsigned long long r;
    asm("mov.b64 %0, {%1, %2};" : "=l"(r) : "r"(__float_as_uint(a)), "r"(__float_as_uint(b)));
    return r;
}
__device__ __forceinline__ float2 unpack2(unsigned long long v){
    unsigned int lo, hi;
    asm("mov.b64 {%0, %1}, %2;" : "=r"(lo), "=r"(hi) : "l"(v));
    return make_float2(__uint_as_float(lo), __uint_as_float(hi));
}

// ---------------- init ----------------
__global__ void k_init(const float* __restrict__ cw){
    int t = blockIdx.x*blockDim.x + threadIdx.x;
    if (t < BB*KK*CC) g_agg[t] = 0.f;
    int t2 = t - BB*KK*CC;
    if (t2 >= 0 && t2 < BB*KK) g_wsum[t2] = 0.f;
    if (t < KK){
        float s = 0.f;
        #pragma unroll 8
        for (int c = 0; c < CC; c++){ float v = cw[t*CC + c]; s += v*v; }
        g_c2[t] = s;
    }
}

// ---------------- fused encode ----------------
// smem floats:
//  [0,16384)       x tile  [64][256]
//  [16384,24576)   cw      [c4=64][k=32] float4 chunks
//  [24576,26624)   w       [64][32]
//  [26624,26752)   x2 partials [128]  (x2[p] = p2[2p]+p2[2p+1])
#define SMEM_FLOATS 26752
#define SMEM_BYTES  (SMEM_FLOATS*4)

__global__ __launch_bounds__(TPB, 2) void k_encode(
    const float* __restrict__ x,
    const float* __restrict__ cw,
    const float* __restrict__ smo)
{
    extern __shared__ float smem[];
    float* sm_x   = smem;
    float* sm_cw  = smem + 16384;
    float* sm_w   = smem + 24576;
    float* sm_x2p = smem + 26624;

    const int t = threadIdx.x;
    const int lane = t & 31;
    const int warp = t >> 5;

    // codewords -> smem [c4][k] (once per block)
    #pragma unroll
    for (int i = 0; i < 4; i++){
        int idx = t + i*TPB;               // 0..2047
        int k  = idx >> 6;
        int c4 = idx & 63;
        float4 v = ((const float4*)cw)[k*64 + c4];
        ((float4*)sm_cw)[c4*32 + k] = v;
    }
    const float sk_r  = smo[lane];
    const float c2_r  = g_c2[lane];

    // persistent aggregation accumulators: 2 k x 8 c per thread
    unsigned long long accC[8];
    #pragma unroll
    for (int i = 0; i < 8; i++) accC[i] = 0ULL;
    float wsum_loc = 0.f;

    const int p0 = warp * 4;           // phase B pixels
    const int k0 = (t & 15) * 2;       // phase C k pair
    const int c8 = (t >> 4) * 8;       // phase C c group

    const int tile0 = blockIdx.x * TILES_PER_BLOCK;
    int cur_b = -1;

    for (int it = 0; it < TILES_PER_BLOCK; it++){
        const int tile = tile0 + it;
        if (tile >= TILES_TOTAL) break;
        const int b = tile >> 8;                 // 256 tiles per batch

        if (b != cur_b){
            if (cur_b >= 0){
                // flush accumulators for previous batch
                #pragma unroll
                for (int kk = 0; kk < 2; kk++)
                    #pragma unroll
                    for (int j = 0; j < 4; j++){
                        float2 f = unpack2(accC[kk*4+j]);
                        float* dst = &g_agg[(cur_b*KK + k0 + kk)*CC + c8 + j*2];
                        atomicAdd(dst,     f.x);
                        atomicAdd(dst + 1, f.y);
                    }
                atomicAdd(&g_wsum[cur_b*KK + lane], wsum_loc);
                #pragma unroll
                for (int i = 0; i < 8; i++) accC[i] = 0ULL;
                wsum_loc = 0.f;
            }
            cur_b = b;
        }

        __syncthreads();   // prior phase C done with sm_x / sm_w

        // ---- Phase A: load 64x256 tile + fold x^2 partials ----
        {
            const int pbase = (tile & 255) * TILE_P;
            const float4* xg = (const float4*)(x + (size_t)(b*NPIX + pbase)*CC);
            float4 v[8];
            #pragma unroll
            for (int i = 0; i < 8; i++) v[i] = xg[t + i*TPB];
            #pragma unroll
            for (int i = 0; i < 8; i++){
                ((float4*)sm_x)[t + i*TPB] = v[i];
                float part = v[i].x*v[i].x + v[i].y*v[i].y + v[i].z*v[i].z + v[i].w*v[i].w;
                #pragma unroll
                for (int o = 16; o > 0; o >>= 1)
                    part += __shfl_xor_sync(0xffffffffu, part, o);
                if (lane == 0) sm_x2p[warp + i*16] = part;
            }
        }
        __syncthreads();

        // ---- Phase B: dots (lane = k), warp softmax ----
        {
            unsigned long long acc[4] = {0ULL,0ULL,0ULL,0ULL};
            const ulonglong2* xu = (const ulonglong2*)sm_x;   // [p][64]
            const ulonglong2* cu = (const ulonglong2*)sm_cw;  // [c4][32]
            #pragma unroll 4
            for (int c4 = 0; c4 < 64; c4++){
                ulonglong2 cv = cu[c4*32 + lane];
                #pragma unroll
                for (int pp = 0; pp < 4; pp++){
                    ulonglong2 xv = xu[(p0+pp)*64 + c4];
                    fma2(acc[pp], cv.x, xv.x);
                    fma2(acc[pp], cv.y, xv.y);
                }
            }
            #pragma unroll
            for (int pp = 0; pp < 4; pp++){
                float2 f = unpack2(acc[pp]);
                float dot = f.x + f.y;
                float x2 = sm_x2p[(p0+pp)*2] + sm_x2p[(p0+pp)*2 + 1];
                float lg = (x2 - 2.f*dot + c2_r) * sk_r;
                float m = lg;
                #pragma unroll
                for (int o = 16; o > 0; o >>= 1)
                    m = fmaxf(m, __shfl_xor_sync(0xffffffffu, m, o));
                float e = __expf(lg - m);
                float s = e;
                #pragma unroll
                for (int o = 16; o > 0; o >>= 1)
                    s += __shfl_xor_sync(0xffffffffu, s, o);
                float wv = e / s;
                sm_w[(p0+pp)*32 + lane] = wv;
                wsum_loc += wv;
            }
        }
        __syncthreads();

        // ---- Phase C: agg[k][c] += w[p][k] * x[p][c] ----
        {
            #pragma unroll 4
            for (int p = 0; p < TILE_P; p++){
                float2 w2 = *(const float2*)(sm_w + p*32 + k0);
                unsigned long long wa = pack2(w2.x, w2.x);
                unsigned long long wb = pack2(w2.y, w2.y);
                const ulonglong2* xr = (const ulonglong2*)(sm_x + p*CC + c8);
                ulonglong2 xa = xr[0];
                ulonglong2 xb = xr[1];
                fma2(accC[0], wa, xa.x);
                fma2(accC[1], wa, xa.y);
                fma2(accC[2], wa, xb.x);
                fma2(accC[3], wa, xb.y);
                fma2(accC[4], wb, xa.x);
                fma2(accC[5], wb, xa.y);
                fma2(accC[6], wb, xb.x);
                fma2(accC[7], wb, xb.y);
            }
        }
    }

    if (cur_b >= 0){
        #pragma unroll
        for (int kk = 0; kk < 2; kk++)
            #pragma unroll
            for (int j = 0; j < 4; j++){
                float2 f = unpack2(accC[kk*4+j]);
                float* dst = &g_agg[(cur_b*KK + k0 + kk)*CC + c8 + j*2];
                atomicAdd(dst,     f.x);
                atomicAdd(dst + 1, f.y);
            }
        atomicAdd(&g_wsum[cur_b*KK + lane], wsum_loc);
    }
}

// ---------------- heads ----------------
__global__ void k_heads(
    const float* __restrict__ cw,
    const float* __restrict__ gamma, const float* __restrict__ beta,
    const float* __restrict__ mean,  const float* __restrict__ var,
    const float* __restrict__ Wenc,  const float* __restrict__ benc,
    const float* __restrict__ Wse,   const float* __restrict__ bse,
    float* __restrict__ out)
{
    const int b = blockIdx.x;
    const int c = threadIdx.x;
    __shared__ float enc[CC];

    float acc = 0.f;
    #pragma unroll
    for (int k = 0; k < KK; k++){
        float a  = g_agg[(b*KK + k)*CC + c] - g_wsum[b*KK + k] * cw[k*CC + c];
        float bn = (a - mean[k]) * rsqrtf(var[k] + BN_EPS) * gamma[k] + beta[k];
        acc += fmaxf(bn, 0.f);
    }
    enc[c] = acc;
    __syncthreads();

    float s = benc[c];
    #pragma unroll 8
    for (int i = 0; i < CC; i++) s += enc[i] * Wenc[i*CC + c];
    g_attn[b*CC + c] = 1.f / (1.f + __expf(-s));

    if (c < NCLS){
        float s2 = bse[c];
        #pragma unroll 8
        for (int i = 0; i < CC; i++) s2 += enc[i] * Wse[i*NCLS + c];
        out[(size_t)BB*NPIX*CC + b*NCLS + c] = 1.f / (1.f + __expf(-s2));
    }
}

// ---------------- rescale ----------------
__global__ void k_scale(const float* __restrict__ x, float* __restrict__ out){
    const int F4 = NPIX*CC/4;
    int idx = blockIdx.x*blockDim.x + threadIdx.x;
    int b  = idx / F4;
    int r  = idx - b*F4;
    int c4 = r & 63;
    float4 a = ((const float4*)g_attn)[b*64 + c4];
    float4 v = ((const float4*)x)[idx];
    v.x *= a.x; v.y *= a.y; v.z *= a.z; v.w *= a.w;
    ((float4*)out)[idx] = v;
}

extern "C" void kernel_launch(void* const* d_in, const int* in_sizes, int n_in,
                              void* d_out, int out_size)
{
    const float* x     = (const float*)d_in[0];
    const float* cw    = (const float*)d_in[1];
    const float* smo   = (const float*)d_in[2];
    const float* gamma = (const float*)d_in[3];
    const float* beta  = (const float*)d_in[4];
    const float* mean  = (const float*)d_in[5];
    const float* var   = (const float*)d_in[6];
    const float* Wenc  = (const float*)d_in[7];
    const float* benc  = (const float*)d_in[8];
    const float* Wse   = (const float*)d_in[9];
    const float* bse   = (const float*)d_in[10];
    float* out = (float*)d_out;

    cudaFuncSetAttribute(k_encode, cudaFuncAttributeMaxDynamicSharedMemorySize, SMEM_BYTES);

    int init_total = BB*KK*CC + BB*KK;
    k_init<<<(init_total + 255)/256, 256>>>(cw);
    k_encode<<<GRID_ENC, TPB, SMEM_BYTES>>>(x, cw, smo);
    k_heads<<<BB, CC>>>(cw, gamma, beta, mean, var, Wenc, benc, Wse, bse, out);
    k_scale<<<(BB*NPIX*CC/4)/256, 256>>>(x, out);
}

// round 3
// speedup vs baseline: 1.1241x; 1.0040x over previous
#include <cuda_runtime.h>
#include <cstdint>

#define BB 16
#define HH 128
#define WW 128
#define CC 256
#define KK 32
#define NPIX (HH*WW)
#define NCLS 21
#define BN_EPS 1e-3f

#define TPB 512
#define TILE_P 64
#define TILES_TOTAL (BB*(NPIX/TILE_P))   // 4096
#define GRID_ENC 592                      // 148 SMs * 2 blocks * 2 waves
#define TILES_PER_BLOCK 7                 // ceil(4096/592)

// Scratch (no allocations allowed)
__device__ float g_agg[BB*KK*CC];
__device__ float g_wsum[BB*KK];
__device__ float g_attn[BB*CC];
__device__ float g_c2[KK];

// ---- packed f32x2 helpers ----
__device__ __forceinline__ void fma2(unsigned long long &d, unsigned long long a, unsigned long long b){
    asm("fma.rn.f32x2 %0, %1, %2, %0;" : "+l"(d) : "l"(a), "l"(b));
}
__device__ __forceinline__ unsigned long long pack2(float a, float b){
    unsigned long long r;
    asm("mov.b64 %0, {%1, %2};" : "=l"(r) : "r"(__float_as_uint(a)), "r"(__float_as_uint(b)));
    return r;
}
__device__ __forceinline__ float2 unpack2(unsigned long long v){
    unsigned int lo, hi;
    asm("mov.b64 {%0, %1}, %2;" : "=r"(lo), "=r"(hi) : "l"(v));
    return make_float2(__uint_as_float(lo), __uint_as_float(hi));
}

// ---------------- init ----------------
__global__ void k_init(const float* __restrict__ cw){
    int t = blockIdx.x*blockDim.x + threadIdx.x;
    if (t < BB*KK*CC) g_agg[t] = 0.f;
    int t2 = t - BB*KK*CC;
    if (t2 >= 0 && t2 < BB*KK) g_wsum[t2] = 0.f;
    if (t < KK){
        float s = 0.f;
        #pragma unroll 8
        for (int c = 0; c < CC; c++){ float v = cw[t*CC + c]; s += v*v; }
        g_c2[t] = s;
    }
}

// ---------------- fused encode ----------------
// smem floats:
//  [0,16384)       x tile  [64][256]
//  [16384,24576)   cw      [c4=64][k=32] float4 chunks
//  [24576,26624)   w       [64][32]
//  [26624,26752)   x2 partials [128]  (x2[p] = p2[2p]+p2[2p+1])
#define SMEM_FLOATS 26752
#define SMEM_BYTES  (SMEM_FLOATS*4)

__global__ __launch_bounds__(TPB, 2) void k_encode(
    const float* __restrict__ x,
    const float* __restrict__ cw,
    const float* __restrict__ smo)
{
    extern __shared__ float smem[];
    float* sm_x   = smem;
    float* sm_cw  = smem + 16384;
    float* sm_w   = smem + 24576;
    float* sm_x2p = smem + 26624;

    const int t = threadIdx.x;
    const int lane = t & 31;
    const int warp = t >> 5;

    // codewords -> smem [c4][k] (once per block)
    #pragma unroll
    for (int i = 0; i < 4; i++){
        int idx = t + i*TPB;               // 0..2047
        int k  = idx >> 6;
        int c4 = idx & 63;
        float4 v = ((const float4*)cw)[k*64 + c4];
        ((float4*)sm_cw)[c4*32 + k] = v;
    }
    const float sk_r  = smo[lane];
    const float c2_r  = g_c2[lane];

    // persistent aggregation accumulators: 2 k x 8 c per thread
    unsigned long long accC[8];
    #pragma unroll
    for (int i = 0; i < 8; i++) accC[i] = 0ULL;
    float wsum_loc = 0.f;

    const int p0 = warp * 4;           // phase B pixels
    const int k0 = (t & 15) * 2;       // phase C k pair
    const int c8 = (t >> 4) * 8;       // phase C c group

    const int tile0 = blockIdx.x * TILES_PER_BLOCK;
    int cur_b = -1;

    for (int it = 0; it < TILES_PER_BLOCK; it++){
        const int tile = tile0 + it;
        if (tile >= TILES_TOTAL) break;
        const int b = tile >> 8;                 // 256 tiles per batch

        if (b != cur_b){
            if (cur_b >= 0){
                // flush accumulators for previous batch
                #pragma unroll
                for (int kk = 0; kk < 2; kk++)
                    #pragma unroll
                    for (int j = 0; j < 4; j++){
                        float2 f = unpack2(accC[kk*4+j]);
                        float* dst = &g_agg[(cur_b*KK + k0 + kk)*CC + c8 + j*2];
                        atomicAdd(dst,     f.x);
                        atomicAdd(dst + 1, f.y);
                    }
                atomicAdd(&g_wsum[cur_b*KK + lane], wsum_loc);
                #pragma unroll
                for (int i = 0; i < 8; i++) accC[i] = 0ULL;
                wsum_loc = 0.f;
            }
            cur_b = b;
        }

        __syncthreads();   // prior phase C done with sm_x / sm_w

        // ---- Phase A: load 64x256 tile + fold x^2 partials ----
        {
            const int pbase = (tile & 255) * TILE_P;
            const float4* xg = (const float4*)(x + (size_t)(b*NPIX + pbase)*CC);
            float4 v[8];
            #pragma unroll
            for (int i = 0; i < 8; i++) v[i] = xg[t + i*TPB];
            #pragma unroll
            for (int i = 0; i < 8; i++){
                ((float4*)sm_x)[t + i*TPB] = v[i];
                float part = v[i].x*v[i].x + v[i].y*v[i].y + v[i].z*v[i].z + v[i].w*v[i].w;
                #pragma unroll
                for (int o = 16; o > 0; o >>= 1)
                    part += __shfl_xor_sync(0xffffffffu, part, o);
                if (lane == 0) sm_x2p[warp + i*16] = part;
            }
        }
        __syncthreads();

        // ---- Phase B: dots (lane = k), warp softmax ----
        {
            unsigned long long acc[4] = {0ULL,0ULL,0ULL,0ULL};
            const ulonglong2* xu = (const ulonglong2*)sm_x;   // [p][64]
            const ulonglong2* cu = (const ulonglong2*)sm_cw;  // [c4][32]
            #pragma unroll 4
            for (int c4 = 0; c4 < 64; c4++){
                ulonglong2 cv = cu[c4*32 + lane];
                #pragma unroll
                for (int pp = 0; pp < 4; pp++){
                    ulonglong2 xv = xu[(p0+pp)*64 + c4];
                    fma2(acc[pp], cv.x, xv.x);
                    fma2(acc[pp], cv.y, xv.y);
                }
            }
            #pragma unroll
            for (int pp = 0; pp < 4; pp++){
                float2 f = unpack2(acc[pp]);
                float dot = f.x + f.y;
                float x2 = sm_x2p[(p0+pp)*2] + sm_x2p[(p0+pp)*2 + 1];
                float lg = (x2 - 2.f*dot + c2_r) * sk_r;
                float m = lg;
                #pragma unroll
                for (int o = 16; o > 0; o >>= 1)
                    m = fmaxf(m, __shfl_xor_sync(0xffffffffu, m, o));
                float e = __expf(lg - m);
                float s = e;
                #pragma unroll
                for (int o = 16; o > 0; o >>= 1)
                    s += __shfl_xor_sync(0xffffffffu, s, o);
                float wv = e / s;
                sm_w[(p0+pp)*32 + lane] = wv;
                wsum_loc += wv;
            }
        }
        __syncthreads();

        // ---- Phase C: agg[k][c] += w[p][k] * x[p][c] ----
        {
            #pragma unroll 4
            for (int p = 0; p < TILE_P; p++){
                float2 w2 = *(const float2*)(sm_w + p*32 + k0);
                unsigned long long wa = pack2(w2.x, w2.x);
                unsigned long long wb = pack2(w2.y, w2.y);
                const ulonglong2* xr = (const ulonglong2*)(sm_x + p*CC + c8);
                ulonglong2 xa = xr[0];
                ulonglong2 xb = xr[1];
                fma2(accC[0], wa, xa.x);
                fma2(accC[1], wa, xa.y);
                fma2(accC[2], wa, xb.x);
                fma2(accC[3], wa, xb.y);
                fma2(accC[4], wb, xa.x);
                fma2(accC[5], wb, xa.y);
                fma2(accC[6], wb, xb.x);
                fma2(accC[7], wb, xb.y);
            }
        }
    }

    if (cur_b >= 0){
        #pragma unroll
        for (int kk = 0; kk < 2; kk++)
            #pragma unroll
            for (int j = 0; j < 4; j++){
                float2 f = unpack2(accC[kk*4+j]);
                float* dst = &g_agg[(cur_b*KK + k0 + kk)*CC + c8 + j*2];
                atomicAdd(dst,     f.x);
                atomicAdd(dst + 1, f.y);
            }
        atomicAdd(&g_wsum[cur_b*KK + lane], wsum_loc);
    }
}

// ---------------- heads ----------------
__global__ void k_heads(
    const float* __restrict__ cw,
    const float* __restrict__ gamma, const float* __restrict__ beta,
    const float* __restrict__ mean,  const float* __restrict__ var,
    const float* __restrict__ Wenc,  const float* __restrict__ benc,
    const float* __restrict__ Wse,   const float* __restrict__ bse,
    float* __restrict__ out)
{
    const int b = blockIdx.x;
    const int c = threadIdx.x;
    __shared__ float enc[CC];

    float acc = 0.f;
    #pragma unroll
    for (int k = 0; k < KK; k++){
        float a  = g_agg[(b*KK + k)*CC + c] - g_wsum[b*KK + k] * cw[k*CC + c];
        float bn = (a - mean[k]) * rsqrtf(var[k] + BN_EPS) * gamma[k] + beta[k];
        acc += fmaxf(bn, 0.f);
    }
    enc[c] = acc;
    __syncthreads();

    float s = benc[c];
    #pragma unroll 8
    for (int i = 0; i < CC; i++) s += enc[i] * Wenc[i*CC + c];
    g_attn[b*CC + c] = 1.f / (1.f + __expf(-s));

    if (c < NCLS){
        float s2 = bse[c];
        #pragma unroll 8
        for (int i = 0; i < CC; i++) s2 += enc[i] * Wse[i*NCLS + c];
        out[(size_t)BB*NPIX*CC + b*NCLS + c] = 1.f / (1.f + __expf(-s2));
    }
}

// ---------------- rescale ----------------
__global__ void k_scale(const float* __restrict__ x, float* __restrict__ out){
    const int F4 = NPIX*CC/4;
    int idx = blockIdx.x*blockDim.x + threadIdx.x;
    int b  = idx / F4;
    int r  = idx - b*F4;
    int c4 = r & 63;
    float4 a = ((const float4*)g_attn)[b*64 + c4];
    float4 v = ((const float4*)x)[idx];
    v.x *= a.x; v.y *= a.y; v.z *= a.z; v.w *= a.w;
    ((float4*)out)[idx] = v;
}

extern "C" void kernel_launch(void* const* d_in, const int* in_sizes, int n_in,
                              void* d_out, int out_size)
{
    const float* x     = (const float*)d_in[0];
    const float* cw    = (const float*)d_in[1];
    const float* smo   = (const float*)d_in[2];
    const float* gamma = (const float*)d_in[3];
    const float* beta  = (const float*)d_in[4];
    const float* mean  = (const float*)d_in[5];
    const float* var   = (const float*)d_in[6];
    const float* Wenc  = (const float*)d_in[7];
    const float* benc  = (const float*)d_in[8];
    const float* Wse   = (const float*)d_in[9];
    const float* bse   = (const float*)d_in[10];
    float* out = (float*)d_out;

    cudaFuncSetAttribute(k_encode, cudaFuncAttributeMaxDynamicSharedMemorySize, SMEM_BYTES);

    int init_total = BB*KK*CC + BB*KK;
    k_init<<<(init_total + 255)/256, 256>>>(cw);
    k_encode<<<GRID_ENC, TPB, SMEM_BYTES>>>(x, cw, smo);
    k_heads<<<BB, CC>>>(cw, gamma, beta, mean, var, Wenc, benc, Wse, bse, out);
    k_scale<<<(BB*NPIX*CC/4)/256, 256>>>(x, out);
}

// round 6
// speedup vs baseline: 1.1702x; 1.0411x over previous
#include <cuda_runtime.h>
#include <cuda_bf16.h>
#include <cstdint>

#define BB 16
#define HH 128
#define WW 128
#define CC 256
#define KK 32
#define NPIX (HH*WW)
#define NCLS 21
#define BN_EPS 1e-3f

// ---------- encode config ----------
#define TILE_P 64
#define TPB_ENC 256
#define BLOCKS_PER_BATCH 16
#define GRID_ENC (BB*BLOCKS_PER_BATCH)   // 256
#define TILES_PER_BLOCK 16               // 256 tiles/batch / 16 blocks

// smem pitches
#define PX2   528     // x row pitch bytes (264 bf16)
#define PCW2  528
#define PWT2  144     // wT row pitch bytes (72 bf16)
#define PD1   34      // d1 row pitch floats

// smem byte offsets (wT_hi overlays D1: D1 dead after softmax reads it)
#define XHIO  0                    // 64*528 = 33792
#define XLOO  33792                // 33792
#define CWHIO 67584                // 32*528 = 16896
#define CWLOO 84480                // 16896
#define D1O   101376               // 64*34*4 = 8704
#define WTHIO D1O                  // 32*144 = 4608 (overlay)
#define WTLOO 110080               // 4608
#define X2O   114688               // 256
#define SMEM_ENC 114944

// ---------------- scratch ----------------
__device__ float g_agg[BB*KK*CC];
__device__ float g_wsum[BB*KK];
__device__ float g_attn[BB*CC];
__device__ float g_c2[KK];

// ---------------- helpers ----------------
__device__ __forceinline__ uint32_t smem_u32(const void* p){
    uint32_t a;
    asm("{ .reg .u64 t; cvta.to.shared.u64 t, %1; cvt.u32.u64 %0, t; }" : "=r"(a) : "l"(p));
    return a;
}
__device__ __forceinline__ void ldsm4(uint32_t* r, uint32_t addr){
    asm volatile("ldmatrix.sync.aligned.m8n8.x4.shared.b16 {%0,%1,%2,%3}, [%4];"
        : "=r"(r[0]),"=r"(r[1]),"=r"(r[2]),"=r"(r[3]) : "r"(addr));
}
__device__ __forceinline__ void ldsm4t(uint32_t* r, uint32_t addr){
    asm volatile("ldmatrix.sync.aligned.m8n8.x4.trans.shared.b16 {%0,%1,%2,%3}, [%4];"
        : "=r"(r[0]),"=r"(r[1]),"=r"(r[2]),"=r"(r[3]) : "r"(addr));
}
__device__ __forceinline__ void mma16816(float &d0,float &d1,float &d2,float &d3,
    uint32_t a0,uint32_t a1,uint32_t a2,uint32_t a3,uint32_t b0,uint32_t b1){
    asm volatile("mma.sync.aligned.m16n8k16.row.col.f32.bf16.bf16.f32 "
        "{%0,%1,%2,%3}, {%4,%5,%6,%7}, {%8,%9}, {%0,%1,%2,%3};"
        : "+f"(d0),"+f"(d1),"+f"(d2),"+f"(d3)
        : "r"(a0),"r"(a1),"r"(a2),"r"(a3),"r"(b0),"r"(b1));
}
__device__ __forceinline__ uint32_t pack_bf16x2(float a, float b){
    __nv_bfloat162 h = __floats2bfloat162_rn(a, b);
    return *(uint32_t*)&h;
}
__device__ __forceinline__ uint2 hi2(float4 v){
    return make_uint2(pack_bf16x2(v.x, v.y), pack_bf16x2(v.z, v.w));
}
__device__ __forceinline__ float4 residual(float4 v, uint2 h){
    __nv_bfloat162 a = *(__nv_bfloat162*)&h.x;
    __nv_bfloat162 b = *(__nv_bfloat162*)&h.y;
    return make_float4(v.x - __bfloat162float(a.x), v.y - __bfloat162float(a.y),
                       v.z - __bfloat162float(b.x), v.w - __bfloat162float(b.y));
}

// ---------------- init ----------------
__global__ void k_init(const float* __restrict__ cw){
    int t = blockIdx.x*blockDim.x + threadIdx.x;
    if (t < BB*KK*CC) g_agg[t] = 0.f;
    int t2 = t - BB*KK*CC;
    if (t2 >= 0 && t2 < BB*KK) g_wsum[t2] = 0.f;
    if (t < KK){
        float s = 0.f;
        #pragma unroll 8
        for (int c = 0; c < CC; c++){ float v = cw[t*CC + c]; s += v*v; }
        g_c2[t] = s;
    }
}

// ---------------- fused encode (mma.sync bf16, hi/lo splits on all operands) ----------------
__global__ __launch_bounds__(TPB_ENC, 2) void k_encode(
    const float* __restrict__ x,
    const float* __restrict__ cw,
    const float* __restrict__ smo)
{
    extern __shared__ char smem[];
    const uint32_t sb = smem_u32(smem);
    float* sm_d1 = (float*)(smem + D1O);
    float* sm_x2 = (float*)(smem + X2O);

    const int t = threadIdx.x;
    const int lane = t & 31;
    const int wid  = t >> 5;
    const int b        = blockIdx.x >> 4;
    const int blk_in_b = blockIdx.x & 15;

    // ---- cw -> bf16 hi+lo smem [k][c], pitch 528B ----
    {
        const int row = t >> 3, seg = t & 7;     // 32 rows x 8 segs of 32 floats
        const float4* crow = (const float4*)(cw + row*CC + seg*32);
        uint4* chdst = (uint4*)(smem + CWHIO + row*PCW2 + seg*64);
        uint4* cldst = (uint4*)(smem + CWLOO + row*PCW2 + seg*64);
        #pragma unroll
        for (int i = 0; i < 4; i++){
            float4 v0 = crow[i*2], v1 = crow[i*2+1];
            uint2 h0 = hi2(v0), h1 = hi2(v1);
            uint2 l0 = hi2(residual(v0, h0)), l1 = hi2(residual(v1, h1));
            chdst[i] = make_uint4(h0.x, h0.y, h1.x, h1.y);
            cldst[i] = make_uint4(l0.x, l0.y, l1.x, l1.y);
        }
    }

    // per-lane softmax constants: k range (lane&3)*8 .. +8
    float c2r[8], smr[8];
    {
        const int k0s = (lane & 3) * 8;
        #pragma unroll
        for (int j = 0; j < 8; j++){ c2r[j] = g_c2[k0s + j]; smr[j] = smo[k0s + j]; }
    }

    // persistent GEMM2 accumulators: warp (m=wid&1, ng=wid>>1), 8 n-tiles x 4
    float accC[8][4];
    #pragma unroll
    for (int i = 0; i < 8; i++)
        #pragma unroll
        for (int j = 0; j < 4; j++) accC[i][j] = 0.f;
    float wsum_acc[8];
    #pragma unroll
    for (int j = 0; j < 8; j++) wsum_acc[j] = 0.f;

    // phase A mapping
    const int pA = t >> 2, qA = t & 3;
    // phase B mapping
    const int mt1 = wid & 3, nh1 = wid >> 2;
    const int r0B = mt1 * 16;
    const uint32_t aoffB = (uint32_t)(r0B + (lane & 15)) * PX2 + (uint32_t)((lane >> 4) * 16);
    const uint32_t boffB = (uint32_t)(nh1*16 + (lane & 7) + ((lane >> 4) << 3)) * PCW2
                         + (uint32_t)(((lane >> 3) & 1) * 16);
    // phase C mapping
    const int m2 = wid & 1, ng = wid >> 1;
    const int kr0 = m2 * 16;
    const int c0C = ng * 64;
    const uint32_t a2off = (uint32_t)(kr0 + (lane & 15)) * PWT2 + (uint32_t)((lane >> 4) * 16);
    const uint32_t b2off = (uint32_t)(lane & 15) * PX2 + (uint32_t)((lane >> 4) * 16);
    const int g4 = lane >> 2, t4 = lane & 3;

    for (int tile = 0; tile < TILES_PER_BLOCK; tile++){
        __syncthreads();   // smem free from previous tile

        // ---- Phase A: load x[64][256], convert hi/lo bf16, x2 ----
        {
            const int pbase = (blk_in_b*TILES_PER_BLOCK + tile) * TILE_P;
            const float4* xr4 = (const float4*)(x + ((size_t)(b*NPIX + pbase + pA))*CC + qA*64);
            char* xh = smem + XHIO + pA*PX2 + qA*128;
            char* xl = smem + XLOO + pA*PX2 + qA*128;
            float x2v = 0.f;
            #pragma unroll
            for (int i2 = 0; i2 < 4; i2++){
                float4 va = xr4[i2*4+0], vb = xr4[i2*4+1], vc = xr4[i2*4+2], vd = xr4[i2*4+3];
                x2v += va.x*va.x + va.y*va.y + va.z*va.z + va.w*va.w;
                x2v += vb.x*vb.x + vb.y*vb.y + vb.z*vb.z + vb.w*vb.w;
                x2v += vc.x*vc.x + vc.y*vc.y + vc.z*vc.z + vc.w*vc.w;
                x2v += vd.x*vd.x + vd.y*vd.y + vd.z*vd.z + vd.w*vd.w;
                uint2 ha = hi2(va), hb = hi2(vb), hc = hi2(vc), hd = hi2(vd);
                uint2 la = hi2(residual(va, ha)), lb = hi2(residual(vb, hb));
                uint2 lc = hi2(residual(vc, hc)), ld = hi2(residual(vd, hd));
                ((uint4*)(xh + i2*32))[0] = make_uint4(ha.x, ha.y, hb.x, hb.y);
                ((uint4*)(xh + i2*32))[1] = make_uint4(hc.x, hc.y, hd.x, hd.y);
                ((uint4*)(xl + i2*32))[0] = make_uint4(la.x, la.y, lb.x, lb.y);
                ((uint4*)(xl + i2*32))[1] = make_uint4(lc.x, lc.y, ld.x, ld.y);
            }
            x2v += __shfl_xor_sync(0xffffffffu, x2v, 1);
            x2v += __shfl_xor_sync(0xffffffffu, x2v, 2);
            if (qA == 0) sm_x2[pA] = x2v;
        }
        __syncthreads();

        // ---- Phase B: D1[64p][32k] = x . cw^T (xhi.cwhi + xlo.cwhi + xhi.cwlo) ----
        {
            float d0[4] = {0,0,0,0}, d1[4] = {0,0,0,0};
            #pragma unroll 4
            for (int kt = 0; kt < 16; kt++){
                uint32_t bfh[4], bfl[4], afh[4], afl[4];
                ldsm4(bfh, sb + CWHIO + boffB + kt*32);
                ldsm4(afh, sb + XHIO  + aoffB + kt*32);
                mma16816(d0[0],d0[1],d0[2],d0[3], afh[0],afh[1],afh[2],afh[3], bfh[0],bfh[1]);
                mma16816(d1[0],d1[1],d1[2],d1[3], afh[0],afh[1],afh[2],afh[3], bfh[2],bfh[3]);
                ldsm4(bfl, sb + CWLOO + boffB + kt*32);
                mma16816(d0[0],d0[1],d0[2],d0[3], afh[0],afh[1],afh[2],afh[3], bfl[0],bfl[1]);
                mma16816(d1[0],d1[1],d1[2],d1[3], afh[0],afh[1],afh[2],afh[3], bfl[2],bfl[3]);
                ldsm4(afl, sb + XLOO  + aoffB + kt*32);
                mma16816(d0[0],d0[1],d0[2],d0[3], afl[0],afl[1],afl[2],afl[3], bfh[0],bfh[1]);
                mma16816(d1[0],d1[1],d1[2],d1[3], afl[0],afl[1],afl[2],afl[3], bfh[2],bfh[3]);
            }
            const int col0 = nh1*16 + t4*2;
            *(float2*)(sm_d1 + (r0B + g4    )*PD1 + col0    ) = make_float2(d0[0], d0[1]);
            *(float2*)(sm_d1 + (r0B + g4 + 8)*PD1 + col0    ) = make_float2(d0[2], d0[3]);
            *(float2*)(sm_d1 + (r0B + g4    )*PD1 + col0 + 8) = make_float2(d1[0], d1[1]);
            *(float2*)(sm_d1 + (r0B + g4 + 8)*PD1 + col0 + 8) = make_float2(d1[2], d1[3]);
        }
        __syncthreads();

        // ---- softmax: pixel p = wid*8 + g4, k range t4*8 ----
        float wv[8];
        {
            const int p = wid*8 + g4;
            const float* drow = sm_d1 + p*PD1 + t4*8;
            const float x2v = sm_x2[p];
            float e[8];
            float mx = -1e30f;
            #pragma unroll
            for (int j = 0; j < 8; j++){
                float lg = (x2v - 2.f*drow[j] + c2r[j]) * smr[j];
                e[j] = lg;
                mx = fmaxf(mx, lg);
            }
            mx = fmaxf(mx, __shfl_xor_sync(0xffffffffu, mx, 1));
            mx = fmaxf(mx, __shfl_xor_sync(0xffffffffu, mx, 2));
            float s = 0.f;
            #pragma unroll
            for (int j = 0; j < 8; j++){ e[j] = __expf(e[j] - mx); s += e[j]; }
            s += __shfl_xor_sync(0xffffffffu, s, 1);
            s += __shfl_xor_sync(0xffffffffu, s, 2);
            const float inv = 1.f / s;
            #pragma unroll
            for (int j = 0; j < 8; j++){
                wv[j] = e[j] * inv;
                wsum_acc[j] += wv[j];
            }
        }
        __syncthreads();   // all D1 reads done before wT_hi overlays D1

        // ---- wT hi/lo write (wT_hi overlays D1 region) ----
        {
            const int p = wid*8 + g4;
            char* wh = smem + WTHIO + (t4*8)*PWT2 + p*2;
            char* wl = smem + WTLOO + (t4*8)*PWT2 + p*2;
            #pragma unroll
            for (int j = 0; j < 8; j++){
                __nv_bfloat16 hb = __float2bfloat16_rn(wv[j]);
                *(__nv_bfloat16*)(wh + j*PWT2) = hb;
                *(__nv_bfloat16*)(wl + j*PWT2) = __float2bfloat16_rn(wv[j] - __bfloat162float(hb));
            }
        }
        __syncthreads();

        // ---- Phase C: agg[32k][256c] += wT . x (whi.xhi + whi.xlo + wlo.xhi) ----
        {
            #pragma unroll
            for (int pt = 0; pt < 4; pt++){
                uint32_t afh[4], afl[4];
                ldsm4(afh, sb + WTHIO + a2off + pt*32);
                ldsm4(afl, sb + WTLOO + a2off + pt*32);
                #pragma unroll
                for (int hf = 0; hf < 4; hf++){
                    const uint32_t bcol = (uint32_t)(c0C + hf*16) * 2;
                    uint32_t bh[4], bl[4];
                    ldsm4t(bh, sb + XHIO + b2off + pt*16*PX2 + bcol);
                    ldsm4t(bl, sb + XLOO + b2off + pt*16*PX2 + bcol);
                    mma16816(accC[hf*2  ][0],accC[hf*2  ][1],accC[hf*2  ][2],accC[hf*2  ][3],
                             afh[0],afh[1],afh[2],afh[3], bh[0],bh[1]);
                    mma16816(accC[hf*2+1][0],accC[hf*2+1][1],accC[hf*2+1][2],accC[hf*2+1][3],
                             afh[0],afh[1],afh[2],afh[3], bh[2],bh[3]);
                    mma16816(accC[hf*2  ][0],accC[hf*2  ][1],accC[hf*2  ][2],accC[hf*2  ][3],
                             afh[0],afh[1],afh[2],afh[3], bl[0],bl[1]);
                    mma16816(accC[hf*2+1][0],accC[hf*2+1][1],accC[hf*2+1][2],accC[hf*2+1][3],
                             afh[0],afh[1],afh[2],afh[3], bl[2],bl[3]);
                    mma16816(accC[hf*2  ][0],accC[hf*2  ][1],accC[hf*2  ][2],accC[hf*2  ][3],
                             afl[0],afl[1],afl[2],afl[3], bh[0],bh[1]);
                    mma16816(accC[hf*2+1][0],accC[hf*2+1][1],accC[hf*2+1][2],accC[hf*2+1][3],
                             afl[0],afl[1],afl[2],afl[3], bh[2],bh[3]);
                }
            }
        }
    }

    // ---- flush agg ----
    {
        const int k1 = kr0 + g4;
        #pragma unroll
        for (int nt = 0; nt < 8; nt++){
            float* base = g_agg + ((size_t)b*KK + k1)*CC + c0C + nt*8 + t4*2;
            atomicAdd(base,            accC[nt][0]);
            atomicAdd(base + 1,        accC[nt][1]);
            atomicAdd(base + 8*CC,     accC[nt][2]);
            atomicAdd(base + 8*CC + 1, accC[nt][3]);
        }
    }
    // ---- flush wsum ----
    {
        #pragma unroll
        for (int j = 0; j < 8; j++){
            float s = wsum_acc[j];
            s += __shfl_xor_sync(0xffffffffu, s, 4);
            s += __shfl_xor_sync(0xffffffffu, s, 8);
            s += __shfl_xor_sync(0xffffffffu, s, 16);
            wsum_acc[j] = s;
        }
        if (lane < 4){
            #pragma unroll
            for (int j = 0; j < 8; j++)
                atomicAdd(&g_wsum[b*KK + lane*8 + j], wsum_acc[j]);
        }
    }
}

// ---------------- heads ----------------
__global__ void k_heads(
    const float* __restrict__ cw,
    const float* __restrict__ gamma, const float* __restrict__ beta,
    const float* __restrict__ mean,  const float* __restrict__ var,
    const float* __restrict__ Wenc,  const float* __restrict__ benc,
    const float* __restrict__ Wse,   const float* __restrict__ bse,
    float* __restrict__ out)
{
    const int b = blockIdx.x;
    const int c = threadIdx.x;
    __shared__ float enc[CC];

    float acc = 0.f;
    #pragma unroll
    for (int k = 0; k < KK; k++){
        float a  = g_agg[(b*KK + k)*CC + c] - g_wsum[b*KK + k] * cw[k*CC + c];
        float bn = (a - mean[k]) * rsqrtf(var[k] + BN_EPS) * gamma[k] + beta[k];
        acc += fmaxf(bn, 0.f);
    }
    enc[c] = acc;
    __syncthreads();

    float s = benc[c];
    #pragma unroll 8
    for (int i = 0; i < CC; i++) s += enc[i] * Wenc[i*CC + c];
    g_attn[b*CC + c] = 1.f / (1.f + __expf(-s));

    if (c < NCLS){
        float s2 = bse[c];
        #pragma unroll 8
        for (int i = 0; i < CC; i++) s2 += enc[i] * Wse[i*NCLS + c];
        out[(size_t)BB*NPIX*CC + b*NCLS + c] = 1.f / (1.f + __expf(-s2));
    }
}

// ---------------- rescale ----------------
__global__ void k_scale(const float* __restrict__ x, float* __restrict__ out){
    const int F4 = NPIX*CC/4;
    int idx = blockIdx.x*blockDim.x + threadIdx.x;
    int b  = idx / F4;
    int r  = idx - b*F4;
    int c4 = r & 63;
    float4 a = ((const float4*)g_attn)[b*64 + c4];
    float4 v = ((const float4*)x)[idx];
    v.x *= a.x; v.y *= a.y; v.z *= a.z; v.w *= a.w;
    ((float4*)out)[idx] = v;
}

extern "C" void kernel_launch(void* const* d_in, const int* in_sizes, int n_in,
                              void* d_out, int out_size)
{
    const float* x     = (const float*)d_in[0];
    const float* cw    = (const float*)d_in[1];
    const float* smo   = (const float*)d_in[2];
    const float* gamma = (const float*)d_in[3];
    const float* beta  = (const float*)d_in[4];
    const float* mean  = (const float*)d_in[5];
    const float* var   = (const float*)d_in[6];
    const float* Wenc  = (const float*)d_in[7];
    const float* benc  = (const float*)d_in[8];
    const float* Wse   = (const float*)d_in[9];
    const float* bse   = (const float*)d_in[10];
    float* out = (float*)d_out;

    cudaFuncSetAttribute(k_encode, cudaFuncAttributeMaxDynamicSharedMemorySize, SMEM_ENC);

    int init_total = BB*KK*CC + BB*KK;
    k_init<<<(init_total + 255)/256, 256>>>(cw);
    k_encode<<<GRID_ENC, TPB_ENC, SMEM_ENC>>>(x, cw, smo);
    k_heads<<<BB, CC>>>(cw, gamma, beta, mean, var, Wenc, benc, Wse, bse, out);
    k_scale<<<(BB*NPIX*CC/4)/256, 256>>>(x, out);
}

// round 7
// speedup vs baseline: 1.8741x; 1.6015x over previous
#include <cuda_runtime.h>
#include <cuda_bf16.h>
#include <cstdint>

#define BB 16
#define HH 128
#define WW 128
#define CC 256
#define KK 32
#define NPIX (HH*WW)
#define NCLS 21
#define BN_EPS 1e-3f

// ---------- encode config ----------
#define TILE_P 64
#define TPB_ENC 512
#define GRID_ENC 148
#define TILES_TOTAL (BB*(NPIX/TILE_P))   // 4096

// smem pitches
#define PX2   528     // x row pitch bytes (264 bf16)
#define PCW2  528
#define PWT2  144     // wT row pitch bytes
#define PD1   34      // d1 row pitch floats

// smem byte offsets (double-buffered x planes)
#define XHI0  0            // 33792
#define XLO0  33792        // 33792
#define XHI1  67584
#define XLO1  101376
#define XBUF_STRIDE 67584
#define CWHIO 135168       // 16896
#define CWLOO 152064       // 16896
#define WTHIO 168960       // 4608
#define WTLOO 173568       // 4608
#define D1O   178176       // 8704
#define X2O0  186880       // 256
#define X2O1  187136       // 256
#define CSO   187392       // c2[32] + smo[32] = 256
#define SMEM_ENC 187648

// ---------------- scratch ----------------
__device__ float g_agg[BB*KK*CC];
__device__ float g_wsum[BB*KK];
__device__ float g_attn[BB*CC];
__device__ float g_c2[KK];

// ---------------- helpers ----------------
__device__ __forceinline__ uint32_t smem_u32(const void* p){
    uint32_t a;
    asm("{ .reg .u64 t; cvta.to.shared.u64 t, %1; cvt.u32.u64 %0, t; }" : "=r"(a) : "l"(p));
    return a;
}
__device__ __forceinline__ void ldsm4(uint32_t* r, uint32_t addr){
    asm volatile("ldmatrix.sync.aligned.m8n8.x4.shared.b16 {%0,%1,%2,%3}, [%4];"
        : "=r"(r[0]),"=r"(r[1]),"=r"(r[2]),"=r"(r[3]) : "r"(addr));
}
__device__ __forceinline__ void ldsm4t(uint32_t* r, uint32_t addr){
    asm volatile("ldmatrix.sync.aligned.m8n8.x4.trans.shared.b16 {%0,%1,%2,%3}, [%4];"
        : "=r"(r[0]),"=r"(r[1]),"=r"(r[2]),"=r"(r[3]) : "r"(addr));
}
__device__ __forceinline__ void mma16816(float &d0,float &d1,float &d2,float &d3,
    uint32_t a0,uint32_t a1,uint32_t a2,uint32_t a3,uint32_t b0,uint32_t b1){
    asm volatile("mma.sync.aligned.m16n8k16.row.col.f32.bf16.bf16.f32 "
        "{%0,%1,%2,%3}, {%4,%5,%6,%7}, {%8,%9}, {%0,%1,%2,%3};"
        : "+f"(d0),"+f"(d1),"+f"(d2),"+f"(d3)
        : "r"(a0),"r"(a1),"r"(a2),"r"(a3),"r"(b0),"r"(b1));
}
__device__ __forceinline__ uint32_t pack_bf16x2(float a, float b){
    __nv_bfloat162 h = __floats2bfloat162_rn(a, b);
    return *(uint32_t*)&h;
}
__device__ __forceinline__ uint2 hi2(float4 v){
    return make_uint2(pack_bf16x2(v.x, v.y), pack_bf16x2(v.z, v.w));
}
__device__ __forceinline__ float4 residual(float4 v, uint2 h){
    __nv_bfloat162 a = *(__nv_bfloat162*)&h.x;
    __nv_bfloat162 b = *(__nv_bfloat162*)&h.y;
    return make_float4(v.x - __bfloat162float(a.x), v.y - __bfloat162float(a.y),
                       v.z - __bfloat162float(b.x), v.w - __bfloat162float(b.y));
}

// ---------------- init ----------------
__global__ void k_init(const float* __restrict__ cw){
    int t = blockIdx.x*blockDim.x + threadIdx.x;
    if (t < BB*KK*CC) g_agg[t] = 0.f;
    int t2 = t - BB*KK*CC;
    if (t2 >= 0 && t2 < BB*KK) g_wsum[t2] = 0.f;
    if (t < KK){
        float s = 0.f;
        #pragma unroll 8
        for (int c = 0; c < CC; c++){ float v = cw[t*CC + c]; s += v*v; }
        g_c2[t] = s;
    }
}

// ---------------- fused encode: pipelined, warp-split mma.sync ----------------
__global__ __launch_bounds__(TPB_ENC, 1) void k_encode(
    const float* __restrict__ x,
    const float* __restrict__ cw,
    const float* __restrict__ smo)
{
    extern __shared__ char smem[];
    const uint32_t sb = smem_u32(smem);
    float* sm_d1 = (float*)(smem + D1O);
    float* sm_c2  = (float*)(smem + CSO);
    float* sm_smo = (float*)(smem + CSO + 128);

    const int t = threadIdx.x;
    const int lane = t & 31;
    const int wid  = t >> 5;

    // ---- cw -> bf16 hi+lo planes (once) ----
    {
        const int row = t >> 4, seg = t & 15;    // 32 rows x 16 segs of 16 floats
        const float4* crow = (const float4*)(cw + row*CC) + seg*4;
        float4 v0 = crow[0], v1 = crow[1], v2 = crow[2], v3 = crow[3];
        uint2 h0 = hi2(v0), h1 = hi2(v1), h2 = hi2(v2), h3 = hi2(v3);
        uint2 l0 = hi2(residual(v0,h0)), l1 = hi2(residual(v1,h1));
        uint2 l2 = hi2(residual(v2,h2)), l3 = hi2(residual(v3,h3));
        char* hdst = smem + CWHIO + row*PCW2 + seg*32;
        char* ldst = smem + CWLOO + row*PCW2 + seg*32;
        ((uint4*)hdst)[0] = make_uint4(h0.x,h0.y,h1.x,h1.y);
        ((uint4*)hdst)[1] = make_uint4(h2.x,h2.y,h3.x,h3.y);
        ((uint4*)ldst)[0] = make_uint4(l0.x,l0.y,l1.x,l1.y);
        ((uint4*)ldst)[1] = make_uint4(l2.x,l2.y,l3.x,l3.y);
    }
    if (t < KK){ sm_c2[t] = g_c2[t]; sm_smo[t] = smo[t]; }

    // accumulators
    float accC[8][4];
    #pragma unroll
    for (int i = 0; i < 8; i++)
        #pragma unroll
        for (int j = 0; j < 4; j++) accC[i][j] = 0.f;
    float wsum_acc[8];
    #pragma unroll
    for (int j = 0; j < 8; j++) wsum_acc[j] = 0.f;

    // tile range (contiguous, balanced)
    const int t0 = (int)(((long long)blockIdx.x     * TILES_TOTAL) / GRID_ENC);
    const int t1 = (int)(((long long)(blockIdx.x+1) * TILES_TOTAL) / GRID_ENC);

    // mappings
    const int pA = t >> 3, qA = t & 7;                 // conversion: 64px x 8 segs of 32
    const int mt1 = wid & 3, nh1 = (wid >> 2) & 1;     // B warps (0-7)
    const int r0B = mt1 * 16;
    const uint32_t aoffB = (uint32_t)(r0B + (lane & 15)) * PX2 + (uint32_t)((lane >> 4) * 16);
    const uint32_t boffB = (uint32_t)(nh1*16 + (lane & 7) + ((lane >> 4) << 3)) * PCW2
                         + (uint32_t)(((lane >> 3) & 1) * 16);
    const int wc = wid & 7;                            // C warps (8-15)
    const int m2 = wc & 1, ng = wc >> 1;
    const int kr0 = m2 * 16;
    const int c0C = ng * 64;
    const uint32_t a2off = (uint32_t)(kr0 + (lane & 15)) * PWT2 + (uint32_t)((lane >> 4) * 16);
    const uint32_t b2off = (uint32_t)(lane & 15) * PX2 + (uint32_t)((lane >> 4) * 16);
    const int g4 = lane >> 2, t4 = lane & 3;

    // ---- prologue: load+convert tile t0 into buf[t0&1] ----
    {
        const float4* xg = (const float4*)(x + ((size_t)(t0*TILE_P + pA))*CC + qA*32);
        float4 v[8];
        #pragma unroll
        for (int i = 0; i < 8; i++) v[i] = xg[i];
        const uint32_t xo = XHI0 + (uint32_t)(t0 & 1)*XBUF_STRIDE;
        char* xh = smem + xo + pA*PX2 + qA*64;
        char* xl = xh + 33792;
        float x2v = 0.f;
        #pragma unroll
        for (int i2 = 0; i2 < 4; i2++){
            float4 va = v[i2*2], vb = v[i2*2+1];
            x2v += va.x*va.x + va.y*va.y + va.z*va.z + va.w*va.w;
            x2v += vb.x*vb.x + vb.y*vb.y + vb.z*vb.z + vb.w*vb.w;
            uint2 ha = hi2(va), hb = hi2(vb);
            uint2 la = hi2(residual(va,ha)), lb = hi2(residual(vb,hb));
            ((uint4*)(xh))[i2] = make_uint4(ha.x, ha.y, hb.x, hb.y);
            ((uint4*)(xl))[i2] = make_uint4(la.x, la.y, lb.x, lb.y);
        }
        x2v += __shfl_xor_sync(0xffffffffu, x2v, 1);
        x2v += __shfl_xor_sync(0xffffffffu, x2v, 2);
        x2v += __shfl_xor_sync(0xffffffffu, x2v, 4);
        if (qA == 0) ((float*)(smem + X2O0 + (t0 & 1)*256))[pA] = x2v;
    }
    __syncthreads();

    for (int tt = t0; tt < t1; tt++){
        const int cur = tt & 1, nxt = cur ^ 1;
        const uint32_t xhiC = XHI0 + (uint32_t)cur*XBUF_STRIDE, xloC = xhiC + 33792;
        const uint32_t xhiN = XHI0 + (uint32_t)nxt*XBUF_STRIDE, xloN = xhiN + 33792;
        const bool haveNext = (tt + 1 < t1);

        // early LDG for tile tt+1 (consumed in stage 2)
        float4 v[8];
        if (haveNext){
            const float4* xg = (const float4*)(x + ((size_t)((tt+1)*TILE_P + pA))*CC + qA*32);
            #pragma unroll
            for (int i = 0; i < 8; i++) v[i] = xg[i];
        }

        // ---- stage 1: warps 0-7 GEMM1(tt); warps 8-15 GEMM2(tt-1) ----
        if (wid < 8){
            float d0[4] = {0,0,0,0}, d1r[4] = {0,0,0,0};
            #pragma unroll 4
            for (int kt = 0; kt < 16; kt++){
                uint32_t bfh[4], bfl[4], afh[4], afl[4];
                ldsm4(bfh, sb + CWHIO + boffB + kt*32);
                ldsm4(afh, sb + xhiC  + aoffB + kt*32);
                mma16816(d0[0],d0[1],d0[2],d0[3], afh[0],afh[1],afh[2],afh[3], bfh[0],bfh[1]);
                mma16816(d1r[0],d1r[1],d1r[2],d1r[3], afh[0],afh[1],afh[2],afh[3], bfh[2],bfh[3]);
                ldsm4(bfl, sb + CWLOO + boffB + kt*32);
                mma16816(d0[0],d0[1],d0[2],d0[3], afh[0],afh[1],afh[2],afh[3], bfl[0],bfl[1]);
                mma16816(d1r[0],d1r[1],d1r[2],d1r[3], afh[0],afh[1],afh[2],afh[3], bfl[2],bfl[3]);
                ldsm4(afl, sb + xloC  + aoffB + kt*32);
                mma16816(d0[0],d0[1],d0[2],d0[3], afl[0],afl[1],afl[2],afl[3], bfh[0],bfh[1]);
                mma16816(d1r[0],d1r[1],d1r[2],d1r[3], afl[0],afl[1],afl[2],afl[3], bfh[2],bfh[3]);
            }
            const int col0 = nh1*16 + t4*2;
            *(float2*)(sm_d1 + (r0B + g4    )*PD1 + col0    ) = make_float2(d0[0], d0[1]);
            *(float2*)(sm_d1 + (r0B + g4 + 8)*PD1 + col0    ) = make_float2(d0[2], d0[3]);
            *(float2*)(sm_d1 + (r0B + g4    )*PD1 + col0 + 8) = make_float2(d1r[0], d1r[1]);
            *(float2*)(sm_d1 + (r0B + g4 + 8)*PD1 + col0 + 8) = make_float2(d1r[2], d1r[3]);
        } else if (tt > t0){
            #pragma unroll
            for (int pt = 0; pt < 4; pt++){
                uint32_t afh[4], afl[4];
                ldsm4(afh, sb + WTHIO + a2off + pt*32);
                ldsm4(afl, sb + WTLOO + a2off + pt*32);
                #pragma unroll
                for (int hf = 0; hf < 4; hf++){
                    const uint32_t bcol = (uint32_t)(c0C + hf*16) * 2;
                    uint32_t bh[4], bl[4];
                    ldsm4t(bh, sb + xhiN + b2off + pt*16*PX2 + bcol);
                    ldsm4t(bl, sb + xloN + b2off + pt*16*PX2 + bcol);
                    mma16816(accC[hf*2  ][0],accC[hf*2  ][1],accC[hf*2  ][2],accC[hf*2  ][3],
                             afh[0],afh[1],afh[2],afh[3], bh[0],bh[1]);
                    mma16816(accC[hf*2+1][0],accC[hf*2+1][1],accC[hf*2+1][2],accC[hf*2+1][3],
                             afh[0],afh[1],afh[2],afh[3], bh[2],bh[3]);
                    mma16816(accC[hf*2  ][0],accC[hf*2  ][1],accC[hf*2  ][2],accC[hf*2  ][3],
                             afh[0],afh[1],afh[2],afh[3], bl[0],bl[1]);
                    mma16816(accC[hf*2+1][0],accC[hf*2+1][1],accC[hf*2+1][2],accC[hf*2+1][3],
                             afh[0],afh[1],afh[2],afh[3], bl[2],bl[3]);
                    mma16816(accC[hf*2  ][0],accC[hf*2  ][1],accC[hf*2  ][2],accC[hf*2  ][3],
                             afl[0],afl[1],afl[2],afl[3], bh[0],bh[1]);
                    mma16816(accC[hf*2+1][0],accC[hf*2+1][1],accC[hf*2+1][2],accC[hf*2+1][3],
                             afl[0],afl[1],afl[2],afl[3], bh[2],bh[3]);
                }
            }
        }
        __syncthreads();

        // ---- batch-boundary flush (agg lags by one tile; both flush batch of tt-1) ----
        if (tt > t0 && (tt >> 8) != ((tt - 1) >> 8)){
            const int bp = (tt - 1) >> 8;
            if (wid >= 8){
                const int k1 = kr0 + g4;
                #pragma unroll
                for (int nt = 0; nt < 8; nt++){
                    float* base = g_agg + ((size_t)bp*KK + k1)*CC + c0C + nt*8 + t4*2;
                    atomicAdd(base,            accC[nt][0]);
                    atomicAdd(base + 1,        accC[nt][1]);
                    atomicAdd(base + 8*CC,     accC[nt][2]);
                    atomicAdd(base + 8*CC + 1, accC[nt][3]);
                    accC[nt][0] = accC[nt][1] = accC[nt][2] = accC[nt][3] = 0.f;
                }
            } else {
                float red[8];
                #pragma unroll
                for (int j = 0; j < 8; j++){
                    float s = wsum_acc[j];
                    s += __shfl_xor_sync(0xffffffffu, s, 4);
                    s += __shfl_xor_sync(0xffffffffu, s, 8);
                    s += __shfl_xor_sync(0xffffffffu, s, 16);
                    red[j] = s;
                    wsum_acc[j] = 0.f;
                }
                if (lane < 4){
                    #pragma unroll
                    for (int j = 0; j < 8; j++)
                        atomicAdd(&g_wsum[bp*KK + lane*8 + j], red[j]);
                }
            }
        }

        // ---- stage 2: softmax(tt) + wT write (warps 0-7); convert tile tt+1 (all) ----
        if (wid < 8){
            const int p = wid*8 + g4;
            const float* drow = sm_d1 + p*PD1 + t4*8;
            const float x2v = ((const float*)(smem + X2O0 + cur*256))[p];
            float e[8];
            float mx = -1e30f;
            #pragma unroll
            for (int j = 0; j < 8; j++){
                float lg = (x2v - 2.f*drow[j] + sm_c2[t4*8 + j]) * sm_smo[t4*8 + j];
                e[j] = lg;
                mx = fmaxf(mx, lg);
            }
            mx = fmaxf(mx, __shfl_xor_sync(0xffffffffu, mx, 1));
            mx = fmaxf(mx, __shfl_xor_sync(0xffffffffu, mx, 2));
            float s = 0.f;
            #pragma unroll
            for (int j = 0; j < 8; j++){ e[j] = __expf(e[j] - mx); s += e[j]; }
            s += __shfl_xor_sync(0xffffffffu, s, 1);
            s += __shfl_xor_sync(0xffffffffu, s, 2);
            const float inv = 1.f / s;
            char* wh = smem + WTHIO + (t4*8)*PWT2 + p*2;
            char* wl = smem + WTLOO + (t4*8)*PWT2 + p*2;
            #pragma unroll
            for (int j = 0; j < 8; j++){
                float wv = e[j] * inv;
                wsum_acc[j] += wv;
                __nv_bfloat16 hb = __float2bfloat16_rn(wv);
                *(__nv_bfloat16*)(wh + j*PWT2) = hb;
                *(__nv_bfloat16*)(wl + j*PWT2) = __float2bfloat16_rn(wv - __bfloat162float(hb));
            }
        }
        if (haveNext){
            char* xh = smem + xhiN + pA*PX2 + qA*64;
            char* xl = smem + xloN + pA*PX2 + qA*64;
            float x2v = 0.f;
            #pragma unroll
            for (int i2 = 0; i2 < 4; i2++){
                float4 va = v[i2*2], vb = v[i2*2+1];
                x2v += va.x*va.x + va.y*va.y + va.z*va.z + va.w*va.w;
                x2v += vb.x*vb.x + vb.y*vb.y + vb.z*vb.z + vb.w*vb.w;
                uint2 ha = hi2(va), hb = hi2(vb);
                uint2 la = hi2(residual(va,ha)), lb = hi2(residual(vb,hb));
                ((uint4*)(xh))[i2] = make_uint4(ha.x, ha.y, hb.x, hb.y);
                ((uint4*)(xl))[i2] = make_uint4(la.x, la.y, lb.x, lb.y);
            }
            x2v += __shfl_xor_sync(0xffffffffu, x2v, 1);
            x2v += __shfl_xor_sync(0xffffffffu, x2v, 2);
            x2v += __shfl_xor_sync(0xffffffffu, x2v, 4);
            if (qA == 0) ((float*)(smem + X2O0 + nxt*256))[pA] = x2v;
        }
        __syncthreads();
    }

    // ---- epilogue: GEMM2 for last tile ----
    if (wid >= 8){
        const uint32_t xhiL = XHI0 + (uint32_t)((t1-1) & 1)*XBUF_STRIDE, xloL = xhiL + 33792;
        #pragma unroll
        for (int pt = 0; pt < 4; pt++){
            uint32_t afh[4], afl[4];
            ldsm4(afh, sb + WTHIO + a2off + pt*32);
            ldsm4(afl, sb + WTLOO + a2off + pt*32);
            #pragma unroll
            for (int hf = 0; hf < 4; hf++){
                const uint32_t bcol = (uint32_t)(c0C + hf*16) * 2;
                uint32_t bh[4], bl[4];
                ldsm4t(bh, sb + xhiL + b2off + pt*16*PX2 + bcol);
                ldsm4t(bl, sb + xloL + b2off + pt*16*PX2 + bcol);
                mma16816(accC[hf*2  ][0],accC[hf*2  ][1],accC[hf*2  ][2],accC[hf*2  ][3],
                         afh[0],afh[1],afh[2],afh[3], bh[0],bh[1]);
                mma16816(accC[hf*2+1][0],accC[hf*2+1][1],accC[hf*2+1][2],accC[hf*2+1][3],
                         afh[0],afh[1],afh[2],afh[3], bh[2],bh[3]);
                mma16816(accC[hf*2  ][0],accC[hf*2  ][1],accC[hf*2  ][2],accC[hf*2  ][3],
                         afh[0],afh[1],afh[2],afh[3], bl[0],bl[1]);
                mma16816(accC[hf*2+1][0],accC[hf*2+1][1],accC[hf*2+1][2],accC[hf*2+1][3],
                         afh[0],afh[1],afh[2],afh[3], bl[2],bl[3]);
                mma16816(accC[hf*2  ][0],accC[hf*2  ][1],accC[hf*2  ][2],accC[hf*2  ][3],
                         afl[0],afl[1],afl[2],afl[3], bh[0],bh[1]);
                mma16816(accC[hf*2+1][0],accC[hf*2+1][1],accC[hf*2+1][2],accC[hf*2+1][3],
                         afl[0],afl[1],afl[2],afl[3], bh[2],bh[3]);
            }
        }
        // final agg flush
        const int bl2 = (t1 - 1) >> 8;
        const int k1 = kr0 + g4;
        #pragma unroll
        for (int nt = 0; nt < 8; nt++){
            float* base = g_agg + ((size_t)bl2*KK + k1)*CC + c0C + nt*8 + t4*2;
            atomicAdd(base,            accC[nt][0]);
            atomicAdd(base + 1,        accC[nt][1]);
            atomicAdd(base + 8*CC,     accC[nt][2]);
            atomicAdd(base + 8*CC + 1, accC[nt][3]);
        }
    } else {
        // final wsum flush
        const int bl2 = (t1 - 1) >> 8;
        float red[8];
        #pragma unroll
        for (int j = 0; j < 8; j++){
            float s = wsum_acc[j];
            s += __shfl_xor_sync(0xffffffffu, s, 4);
            s += __shfl_xor_sync(0xffffffffu, s, 8);
            s += __shfl_xor_sync(0xffffffffu, s, 16);
            red[j] = s;
        }
        if (lane < 4){
            #pragma unroll
            for (int j = 0; j < 8; j++)
                atomicAdd(&g_wsum[bl2*KK + lane*8 + j], red[j]);
        }
    }
}

// ---------------- heads ----------------
__global__ void k_heads(
    const float* __restrict__ cw,
    const float* __restrict__ gamma, const float* __restrict__ beta,
    const float* __restrict__ mean,  const float* __restrict__ var,
    const float* __restrict__ Wenc,  const float* __restrict__ benc,
    const float* __restrict__ Wse,   const float* __restrict__ bse,
    float* __restrict__ out)
{
    const int b = blockIdx.x;
    const int c = threadIdx.x;
    __shared__ float enc[CC];

    float acc = 0.f;
    #pragma unroll
    for (int k = 0; k < KK; k++){
        float a  = g_agg[(b*KK + k)*CC + c] - g_wsum[b*KK + k] * cw[k*CC + c];
        float bn = (a - mean[k]) * rsqrtf(var[k] + BN_EPS) * gamma[k] + beta[k];
        acc += fmaxf(bn, 0.f);
    }
    enc[c] = acc;
    __syncthreads();

    float s = benc[c];
    #pragma unroll 8
    for (int i = 0; i < CC; i++) s += enc[i] * Wenc[i*CC + c];
    g_attn[b*CC + c] = 1.f / (1.f + __expf(-s));

    if (c < NCLS){
        float s2 = bse[c];
        #pragma unroll 8
        for (int i = 0; i < CC; i++) s2 += enc[i] * Wse[i*NCLS + c];
        out[(size_t)BB*NPIX*CC + b*NCLS + c] = 1.f / (1.f + __expf(-s2));
    }
}

// ---------------- rescale ----------------
__global__ void k_scale(const float* __restrict__ x, float* __restrict__ out){
    const int F4 = NPIX*CC/4;
    int idx = blockIdx.x*blockDim.x + threadIdx.x;
    int b  = idx / F4;
    int r  = idx - b*F4;
    int c4 = r & 63;
    float4 a = ((const float4*)g_attn)[b*64 + c4];
    float4 v = __ldcs((const float4*)x + idx);
    v.x *= a.x; v.y *= a.y; v.z *= a.z; v.w *= a.w;
    __stcs((float4*)out + idx, v);
}

extern "C" void kernel_launch(void* const* d_in, const int* in_sizes, int n_in,
                              void* d_out, int out_size)
{
    const float* x     = (const float*)d_in[0];
    const float* cw    = (const float*)d_in[1];
    const float* smo   = (const float*)d_in[2];
    const float* gamma = (const float*)d_in[3];
    const float* beta  = (const float*)d_in[4];
    const float* mean  = (const float*)d_in[5];
    const float* var   = (const float*)d_in[6];
    const float* Wenc  = (const float*)d_in[7];
    const float* benc  = (const float*)d_in[8];
    const float* Wse   = (const float*)d_in[9];
    const float* bse   = (const float*)d_in[10];
    float* out = (float*)d_out;

    cudaFuncSetAttribute(k_encode, cudaFuncAttributeMaxDynamicSharedMemorySize, SMEM_ENC);

    int init_total = BB*KK*CC + BB*KK;
    k_init<<<(init_total + 255)/256, 256>>>(cw);
    k_encode<<<GRID_ENC, TPB_ENC, SMEM_ENC>>>(x, cw, smo);
    k_heads<<<BB, CC>>>(cw, gamma, beta, mean, var, Wenc, benc, Wse, bse, out);
    k_scale<<<(BB*NPIX*CC/4)/256, 256>>>(x, out);
}

// round 8
// speedup vs baseline: 1.9255x; 1.0274x over previous
#include <cuda_runtime.h>
#include <cuda_fp16.h>
#include <cstdint>

#define BB 16
#define HH 128
#define WW 128
#define CC 256
#define KK 32
#define NPIX (HH*WW)
#define NCLS 21
#define BN_EPS 1e-3f

// ---------- encode config ----------
#define TILE_P 64
#define TPB_ENC 512
#define GRID_ENC 148
#define TILES_TOTAL (BB*(NPIX/TILE_P))   // 4096

// smem pitches (bytes)
#define PX2   528     // x row pitch (256 fp16 + pad)
#define PCW2  528
#define PWT2  144     // wT row pitch (64 fp16 + pad)

// smem layout
#define XBUF  67584                // per-buffer: xhi 33792 + xlo 33792
// xhi(p) = p*XBUF ; xlo(p) = p*XBUF + 33792
#define CWO   135168               // 32*528 = 16896 (fp16 hi only)
#define WT0   152064               // whi(p) = WT0 + p*9216 ; wlo(p) = +4608
#define X2OO  170496               // x2(p) = X2OO + p*256
#define SMEM_ENC 171008

// ---------------- scratch ----------------
__device__ float g_agg[BB*KK*CC];
__device__ float g_wsum[BB*KK];
__device__ float g_attn[BB*CC];
__device__ float g_c2[KK];

// ---------------- helpers ----------------
__device__ __forceinline__ uint32_t smem_u32(const void* p){
    uint32_t a;
    asm("{ .reg .u64 t; cvta.to.shared.u64 t, %1; cvt.u32.u64 %0, t; }" : "=r"(a) : "l"(p));
    return a;
}
__device__ __forceinline__ void ldsm4(uint32_t* r, uint32_t addr){
    asm volatile("ldmatrix.sync.aligned.m8n8.x4.shared.b16 {%0,%1,%2,%3}, [%4];"
        : "=r"(r[0]),"=r"(r[1]),"=r"(r[2]),"=r"(r[3]) : "r"(addr));
}
__device__ __forceinline__ void ldsm4t(uint32_t* r, uint32_t addr){
    asm volatile("ldmatrix.sync.aligned.m8n8.x4.trans.shared.b16 {%0,%1,%2,%3}, [%4];"
        : "=r"(r[0]),"=r"(r[1]),"=r"(r[2]),"=r"(r[3]) : "r"(addr));
}
__device__ __forceinline__ void mmah(float* d,
    const uint32_t* a, uint32_t b0, uint32_t b1){
    asm volatile("mma.sync.aligned.m16n8k16.row.col.f32.f16.f16.f32 "
        "{%0,%1,%2,%3}, {%4,%5,%6,%7}, {%8,%9}, {%0,%1,%2,%3};"
        : "+f"(d[0]),"+f"(d[1]),"+f"(d[2]),"+f"(d[3])
        : "r"(a[0]),"r"(a[1]),"r"(a[2]),"r"(a[3]),"r"(b0),"r"(b1));
}
__device__ __forceinline__ uint32_t pack_h2(float a, float b){
    __half2 h = __floats2half2_rn(a, b);
    return *(uint32_t*)&h;
}
__device__ __forceinline__ uint2 hi2h(float4 v){
    return make_uint2(pack_h2(v.x, v.y), pack_h2(v.z, v.w));
}
__device__ __forceinline__ float4 residual_h(float4 v, uint2 h){
    __half2 a = *(__half2*)&h.x;
    __half2 b = *(__half2*)&h.y;
    return make_float4(v.x - __half2float(a.x), v.y - __half2float(a.y),
                       v.z - __half2float(b.x), v.w - __half2float(b.y));
}

// ---------------- init ----------------
__global__ void k_init(const float* __restrict__ cw){
    int t = blockIdx.x*blockDim.x + threadIdx.x;
    if (t < BB*KK*CC) g_agg[t] = 0.f;
    int t2 = t - BB*KK*CC;
    if (t2 >= 0 && t2 < BB*KK) g_wsum[t2] = 0.f;
    if (t < KK){
        float s = 0.f;
        #pragma unroll 8
        for (int c = 0; c < CC; c++){ float v = cw[t*CC + c]; s += v*v; }
        g_c2[t] = s;
    }
}

// ---------------- fused encode ----------------
__global__ __launch_bounds__(TPB_ENC, 1) void k_encode(
    const float* __restrict__ x,
    const float* __restrict__ cw,
    const float* __restrict__ smo)
{
    extern __shared__ char smem[];
    const uint32_t sb = smem_u32(smem);
    const int t = threadIdx.x;
    const int lane = t & 31;
    const int wid  = t >> 5;
    const int g4 = lane >> 2, t4 = lane & 3;

    // ---- cw -> fp16 hi plane (once) ----
    {
        const int row = t >> 4, seg = t & 15;    // 32 rows x 16 segs of 16 floats
        const float4* crow = (const float4*)(cw + row*CC) + seg*4;
        float4 v0 = crow[0], v1 = crow[1], v2 = crow[2], v3 = crow[3];
        uint2 h0 = hi2h(v0), h1 = hi2h(v1), h2 = hi2h(v2), h3 = hi2h(v3);
        char* hdst = smem + CWO + row*PCW2 + seg*32;
        ((uint4*)hdst)[0] = make_uint4(h0.x,h0.y,h1.x,h1.y);
        ((uint4*)hdst)[1] = make_uint4(h2.x,h2.y,h3.x,h3.y);
    }

    // B-warp per-thread softmax constants: k = (j>>1)*8 + t4*2 + (j&1)
    float c2r[8], smr[8];
    if (wid < 4){
        #pragma unroll
        for (int j = 0; j < 8; j++){
            int k = (j >> 1)*8 + t4*2 + (j & 1);
            c2r[j] = g_c2[k]; smr[j] = smo[k];
        }
    }

    // accumulators
    float accC[16][4];
    #pragma unroll
    for (int i = 0; i < 16; i++)
        #pragma unroll
        for (int j = 0; j < 4; j++) accC[i][j] = 0.f;
    float wsum_acc[8];
    #pragma unroll
    for (int j = 0; j < 8; j++) wsum_acc[j] = 0.f;

    // tile range
    const int t0 = (int)(((long long)blockIdx.x     * TILES_TOTAL) / GRID_ENC);
    const int t1 = (int)(((long long)(blockIdx.x+1) * TILES_TOTAL) / GRID_ENC);

    // mappings
    const int pA = t >> 3, qA = t & 7;   // conversion: 64 rows x 8 segs of 32 floats
    // GEMM1 (warps 0-3)
    const uint32_t aoff1 = (uint32_t)(wid*16 + (lane & 15)) * PX2 + (uint32_t)((lane >> 4) * 16);
    const uint32_t boff1 = (uint32_t)((lane & 7) + ((lane >> 4) << 3)) * PCW2
                         + (uint32_t)(((lane >> 3) & 1) * 16);
    // GEMM2 (warps 4-15): term s, sub
    const int wc = wid - 4;
    const int s2 = wc >> 2, sub = wc & 3;
    const int m2 = sub & 1, nh = sub >> 1;
    const uint32_t a2off = (uint32_t)(m2*16 + (lane & 15)) * PWT2 + (uint32_t)((lane >> 4) * 16);
    const uint32_t b2off = (uint32_t)(lane & 15) * PX2 + (uint32_t)((lane >> 4) * 16);

    // ---- prologue: convert tile t0 into buf[t0&1] ----
    {
        const float4* xg = (const float4*)(x + ((size_t)(t0*TILE_P + pA))*CC + qA*32);
        float4 v[8];
        #pragma unroll
        for (int i = 0; i < 8; i++) v[i] = xg[i];
        const uint32_t xo = (uint32_t)(t0 & 1)*XBUF;
        char* xh = smem + xo + pA*PX2 + qA*64;
        char* xl = xh + 33792;
        float x2v = 0.f;
        #pragma unroll
        for (int i2 = 0; i2 < 4; i2++){
            float4 va = v[i2*2], vb = v[i2*2+1];
            x2v += va.x*va.x + va.y*va.y + va.z*va.z + va.w*va.w;
            x2v += vb.x*vb.x + vb.y*vb.y + vb.z*vb.z + vb.w*vb.w;
            uint2 ha = hi2h(va), hb = hi2h(vb);
            uint2 la = hi2h(residual_h(va,ha)), lb = hi2h(residual_h(vb,hb));
            ((uint4*)(xh))[i2] = make_uint4(ha.x, ha.y, hb.x, hb.y);
            ((uint4*)(xl))[i2] = make_uint4(la.x, la.y, lb.x, lb.y);
        }
        x2v += __shfl_xor_sync(0xffffffffu, x2v, 1);
        x2v += __shfl_xor_sync(0xffffffffu, x2v, 2);
        x2v += __shfl_xor_sync(0xffffffffu, x2v, 4);
        if (qA == 0) ((float*)(smem + X2OO + (t0 & 1)*256))[pA] = x2v;
    }
    __syncthreads();

    for (int tt = t0; tt < t1; tt++){
        const int cur = tt & 1, nxt = cur ^ 1;
        const uint32_t xhiC = (uint32_t)cur*XBUF, xloC = xhiC + 33792;
        const uint32_t xhiN = (uint32_t)nxt*XBUF, xloN = xhiN + 33792;

        const bool boundary = (tt > t0) && ((tt >> 8) != ((tt - 1) >> 8));
        const int bp = (tt - 1) >> 8;

        // B-warps: wsum flush at top (covers tiles <= tt-1)
        if (wid < 4 && boundary){
            float red[8];
            #pragma unroll
            for (int j = 0; j < 8; j++){
                float s = wsum_acc[j];
                s += __shfl_xor_sync(0xffffffffu, s, 4);
                s += __shfl_xor_sync(0xffffffffu, s, 8);
                s += __shfl_xor_sync(0xffffffffu, s, 16);
                red[j] = s; wsum_acc[j] = 0.f;
            }
            if (g4 == 0){
                #pragma unroll
                for (int j = 0; j < 8; j++){
                    int k = (j >> 1)*8 + t4*2 + (j & 1);
                    atomicAdd(&g_wsum[bp*KK + k], red[j]);
                }
            }
        }

        // ---- stage 1 ----
        if (wid < 4){
            // GEMM1: D1[p 16][k 32] = xhi . cwhi^T
            float d[4][4];
            #pragma unroll
            for (int i = 0; i < 4; i++)
                #pragma unroll
                for (int j = 0; j < 4; j++) d[i][j] = 0.f;
            #pragma unroll 4
            for (int kt = 0; kt < 16; kt++){
                uint32_t a[4], b0[4], b1[4];
                ldsm4(a,  sb + xhiC + aoff1 + kt*32);
                ldsm4(b0, sb + CWO + boff1 + kt*32);
                ldsm4(b1, sb + CWO + boff1 + 16*PCW2 + kt*32);
                mmah(d[0], a, b0[0], b0[1]);
                mmah(d[1], a, b0[2], b0[3]);
                mmah(d[2], a, b1[0], b1[1]);
                mmah(d[3], a, b1[2], b1[3]);
            }
            // softmax from fragments: px0 = wid*16+g4 (d[nt][0,1]), px1 = +8 (d[nt][2,3])
            const int px0 = wid*16 + g4, px1 = px0 + 8;
            const float* x2p = (const float*)(smem + X2OO + cur*256);
            const float xa = x2p[px0], xb = x2p[px1];
            float ea[8], eb[8];
            float mxa = -1e30f, mxb = -1e30f;
            #pragma unroll
            for (int j = 0; j < 8; j++){
                int nt = j >> 1, i = j & 1;
                float la = (xa - 2.f*d[nt][i]     + c2r[j]) * smr[j];
                float lb = (xb - 2.f*d[nt][2 + i] + c2r[j]) * smr[j];
                ea[j] = la; eb[j] = lb;
                mxa = fmaxf(mxa, la); mxb = fmaxf(mxb, lb);
            }
            mxa = fmaxf(mxa, __shfl_xor_sync(0xffffffffu, mxa, 1));
            mxa = fmaxf(mxa, __shfl_xor_sync(0xffffffffu, mxa, 2));
            mxb = fmaxf(mxb, __shfl_xor_sync(0xffffffffu, mxb, 1));
            mxb = fmaxf(mxb, __shfl_xor_sync(0xffffffffu, mxb, 2));
            float sa = 0.f, sbv = 0.f;
            #pragma unroll
            for (int j = 0; j < 8; j++){
                ea[j] = __expf(ea[j] - mxa); sa  += ea[j];
                eb[j] = __expf(eb[j] - mxb); sbv += eb[j];
            }
            sa  += __shfl_xor_sync(0xffffffffu, sa, 1);
            sa  += __shfl_xor_sync(0xffffffffu, sa, 2);
            sbv += __shfl_xor_sync(0xffffffffu, sbv, 1);
            sbv += __shfl_xor_sync(0xffffffffu, sbv, 2);
            const float inva = 1.f / sa, invb = 1.f / sbv;
            char* wh = smem + WT0 + cur*9216;
            char* wl = wh + 4608;
            #pragma unroll
            for (int j = 0; j < 8; j++){
                int k = (j >> 1)*8 + t4*2 + (j & 1);
                float wa = ea[j]*inva, wb = eb[j]*invb;
                wsum_acc[j] += wa + wb;
                __half ha = __float2half_rn(wa);
                __half hb = __float2half_rn(wb);
                *(__half*)(wh + k*PWT2 + px0*2) = ha;
                *(__half*)(wh + k*PWT2 + px1*2) = hb;
                *(__half*)(wl + k*PWT2 + px0*2) = __float2half_rn(wa - __half2float(ha));
                *(__half*)(wl + k*PWT2 + px1*2) = __float2half_rn(wb - __half2float(hb));
            }
        } else if (tt > t0){
            // GEMM2(tt-1): term s2 in {whi.xhi, whi.xlo, wlo.xhi}
            const uint32_t apl = WT0 + (uint32_t)nxt*9216 + (s2 == 2 ? 4608u : 0u);
            const uint32_t bpl = (s2 == 1) ? xloN : xhiN;
            #pragma unroll
            for (int pt = 0; pt < 4; pt++){
                uint32_t af[4];
                ldsm4(af, sb + apl + a2off + pt*32);
                #pragma unroll
                for (int hf = 0; hf < 8; hf++){
                    uint32_t bf[4];
                    ldsm4t(bf, sb + bpl + b2off + pt*16*PX2 + (uint32_t)(nh*128 + hf*16)*2);
                    mmah(accC[hf*2    ], af, bf[0], bf[1]);
                    mmah(accC[hf*2 + 1], af, bf[2], bf[3]);
                }
            }
        }
        __syncthreads();

        // C-warps: accC flush (covers tiles <= tt-1)
        if (wid >= 4 && boundary){
            const int k1 = m2*16 + g4;
            #pragma unroll
            for (int nt = 0; nt < 16; nt++){
                float* base = g_agg + ((size_t)bp*KK + k1)*CC + nh*128 + nt*8 + t4*2;
                atomicAdd(base,            accC[nt][0]);
                atomicAdd(base + 1,        accC[nt][1]);
                atomicAdd(base + 8*CC,     accC[nt][2]);
                atomicAdd(base + 8*CC + 1, accC[nt][3]);
                accC[nt][0] = accC[nt][1] = accC[nt][2] = accC[nt][3] = 0.f;
            }
        }

        // ---- stage 2: convert tile tt+1 into buf nxt ----
        if (tt + 1 < t1){
            const float4* xg = (const float4*)(x + ((size_t)((tt+1)*TILE_P + pA))*CC + qA*32);
            float4 v[8];
            #pragma unroll
            for (int i = 0; i < 8; i++) v[i] = xg[i];
            char* xh = smem + xhiN + pA*PX2 + qA*64;
            char* xl = smem + xloN + pA*PX2 + qA*64;
            float x2v = 0.f;
            #pragma unroll
            for (int i2 = 0; i2 < 4; i2++){
                float4 va = v[i2*2], vb = v[i2*2+1];
                x2v += va.x*va.x + va.y*va.y + va.z*va.z + va.w*va.w;
                x2v += vb.x*vb.x + vb.y*vb.y + vb.z*vb.z + vb.w*vb.w;
                uint2 ha = hi2h(va), hb = hi2h(vb);
                uint2 la = hi2h(residual_h(va,ha)), lb = hi2h(residual_h(vb,hb));
                ((uint4*)(xh))[i2] = make_uint4(ha.x, ha.y, hb.x, hb.y);
                ((uint4*)(xl))[i2] = make_uint4(la.x, la.y, lb.x, lb.y);
            }
            x2v += __shfl_xor_sync(0xffffffffu, x2v, 1);
            x2v += __shfl_xor_sync(0xffffffffu, x2v, 2);
            x2v += __shfl_xor_sync(0xffffffffu, x2v, 4);
            if (qA == 0) ((float*)(smem + X2OO + nxt*256))[pA] = x2v;
        }
        __syncthreads();
    }

    // ---- epilogue ----
    const int bl2 = (t1 - 1) >> 8;
    if (wid >= 4){
        // GEMM2 for last tile (parity (t1-1)&1)
        const int lp = (t1 - 1) & 1;
        const uint32_t xhiL = (uint32_t)lp*XBUF, xloL = xhiL + 33792;
        const uint32_t apl = WT0 + (uint32_t)lp*9216 + (s2 == 2 ? 4608u : 0u);
        const uint32_t bpl = (s2 == 1) ? xloL : xhiL;
        #pragma unroll
        for (int pt = 0; pt < 4; pt++){
            uint32_t af[4];
            ldsm4(af, sb + apl + a2off + pt*32);
            #pragma unroll
            for (int hf = 0; hf < 8; hf++){
                uint32_t bf[4];
                ldsm4t(bf, sb + bpl + b2off + pt*16*PX2 + (uint32_t)(nh*128 + hf*16)*2);
                mmah(accC[hf*2    ], af, bf[0], bf[1]);
                mmah(accC[hf*2 + 1], af, bf[2], bf[3]);
            }
        }
        const int k1 = m2*16 + g4;
        #pragma unroll
        for (int nt = 0; nt < 16; nt++){
            float* base = g_agg + ((size_t)bl2*KK + k1)*CC + nh*128 + nt*8 + t4*2;
            atomicAdd(base,            accC[nt][0]);
            atomicAdd(base + 1,        accC[nt][1]);
            atomicAdd(base + 8*CC,     accC[nt][2]);
            atomicAdd(base + 8*CC + 1, accC[nt][3]);
        }
    } else {
        float red[8];
        #pragma unroll
        for (int j = 0; j < 8; j++){
            float s = wsum_acc[j];
            s += __shfl_xor_sync(0xffffffffu, s, 4);
            s += __shfl_xor_sync(0xffffffffu, s, 8);
            s += __shfl_xor_sync(0xffffffffu, s, 16);
            red[j] = s;
        }
        if (g4 == 0){
            #pragma unroll
            for (int j = 0; j < 8; j++){
                int k = (j >> 1)*8 + t4*2 + (j & 1);
                atomicAdd(&g_wsum[bl2*KK + k], red[j]);
            }
        }
    }
}

// ---------------- heads ----------------
__global__ void k_heads(
    const float* __restrict__ cw,
    const float* __restrict__ gamma, const float* __restrict__ beta,
    const float* __restrict__ mean,  const float* __restrict__ var,
    const float* __restrict__ Wenc,  const float* __restrict__ benc,
    const float* __restrict__ Wse,   const float* __restrict__ bse,
    float* __restrict__ out)
{
    const int b = blockIdx.x;
    const int c = threadIdx.x;
    __shared__ float enc[CC];

    float acc = 0.f;
    #pragma unroll
    for (int k = 0; k < KK; k++){
        float a  = g_agg[(b*KK + k)*CC + c] - g_wsum[b*KK + k] * cw[k*CC + c];
        float bn = (a - mean[k]) * rsqrtf(var[k] + BN_EPS) * gamma[k] + beta[k];
        acc += fmaxf(bn, 0.f);
    }
    enc[c] = acc;
    __syncthreads();

    float s = benc[c];
    #pragma unroll 8
    for (int i = 0; i < CC; i++) s += enc[i] * Wenc[i*CC + c];
    g_attn[b*CC + c] = 1.f / (1.f + __expf(-s));

    if (c < NCLS){
        float s2 = bse[c];
        #pragma unroll 8
        for (int i = 0; i < CC; i++) s2 += enc[i] * Wse[i*NCLS + c];
        out[(size_t)BB*NPIX*CC + b*NCLS + c] = 1.f / (1.f + __expf(-s2));
    }
}

// ---------------- rescale ----------------
__global__ void k_scale(const float* __restrict__ x, float* __restrict__ out){
    const int F4 = NPIX*CC/4;
    int idx = blockIdx.x*blockDim.x + threadIdx.x;
    int b  = idx / F4;
    int r  = idx - b*F4;
    int c4 = r & 63;
    float4 a = ((const float4*)g_attn)[b*64 + c4];
    float4 v = __ldcs((const float4*)x + idx);
    v.x *= a.x; v.y *= a.y; v.z *= a.z; v.w *= a.w;
    __stcs((float4*)out + idx, v);
}

extern "C" void kernel_launch(void* const* d_in, const int* in_sizes, int n_in,
                              void* d_out, int out_size)
{
    const float* x     = (const float*)d_in[0];
    const float* cw    = (const float*)d_in[1];
    const float* smo   = (const float*)d_in[2];
    const float* gamma = (const float*)d_in[3];
    const float* beta  = (const float*)d_in[4];
    const float* mean  = (const float*)d_in[5];
    const float* var   = (const float*)d_in[6];
    const float* Wenc  = (const float*)d_in[7];
    const float* benc  = (const float*)d_in[8];
    const float* Wse   = (const float*)d_in[9];
    const float* bse   = (const float*)d_in[10];
    float* out = (float*)d_out;

    cudaFuncSetAttribute(k_encode, cudaFuncAttributeMaxDynamicSharedMemorySize, SMEM_ENC);

    int init_total = BB*KK*CC + BB*KK;
    k_init<<<(init_total + 255)/256, 256>>>(cw);
    k_encode<<<GRID_ENC, TPB_ENC, SMEM_ENC>>>(x, cw, smo);
    k_heads<<<BB, CC>>>(cw, gamma, beta, mean, var, Wenc, benc, Wse, bse, out);
    k_scale<<<(BB*NPIX*CC/4)/256, 256>>>(x, out);
}